// round 9
// baseline (speedup 1.0000x reference)
#include <cuda_runtime.h>
#include <cuda_fp16.h>
#include <math.h>

#define Nn 100000
#define Ee 3200000
#define Cc 64
#define AC 0.979f
#define AS 0.756f
#define SCAN_BLK 1024
#define SCAN_NBLK ((Nn + SCAN_BLK - 1) / SCAN_BLK)   // 98
#define GN ((Nn + 255) / 256)                        // 391

// ---------------- static scratch ----------------
__device__ uint4    g_hA[Nn * 8];      // fp16 state rows: 64 halfs = 128B = 8 uint4
__device__ uint4    g_hB[Nn * 8];
__device__ uint4    g_lasth[Nn * 8];
__device__ int      g_deg[Nn];
__device__ int      g_cnt[Nn];         // pre-initialized to rowptr; fill bumps it
__device__ int      g_rowptr[Nn + 1];
__device__ int      g_wq[Nn];          // 15-bit quantized norm per node
__device__ unsigned g_csr[Ee];         // (wq<<17) | src  — 4B per edge
__device__ int      g_blocksums[128];
__device__ float    g_sumabs;
__device__ float    g_nummask;
__device__ int      g_mask_mode;       // 0=uint8, 1=int32, 2=float32

__device__ __forceinline__ bool mask_at(const void* __restrict__ mp, int i) {
    int mode = g_mask_mode;
    if (mode == 1) return ((const int*)mp)[i] != 0;
    if (mode == 2) return ((const float*)mp)[i] != 0.0f;
    return ((const unsigned char*)mp)[i] != 0;
}

// ---------------- init + mask dtype detection ----------------
__global__ void k_init(const void* __restrict__ mp) {
    int i = blockIdx.x * blockDim.x + threadIdx.x;
    if (i < Nn) g_deg[i] = 0;
    if (i == 0) { g_sumabs = 0.f; g_nummask = 0.f; }
    if (blockIdx.x == 0) {
        __shared__ int s_iok, s_fok;
        if (threadIdx.x == 0) { s_iok = 1; s_fok = 1; }
        __syncthreads();
        const int*   ip = (const int*)mp;
        const float* fp = (const float*)mp;
        bool iok = true, fok = true;
        for (int j = threadIdx.x; j < 1024; j += 256) {
            int v = ip[j];
            if (v != 0 && v != 1) iok = false;
            float f = fp[j];
            if (!(f == 0.0f || f == 1.0f)) fok = false;
        }
        if (!iok) s_iok = 0;
        if (!fok) s_fok = 0;
        __syncthreads();
        if (threadIdx.x == 0) g_mask_mode = s_iok ? 1 : (s_fok ? 2 : 0);
    }
}

// ---------------- degree histogram (4 edges / thread) ----------------
__global__ void k_hist(const int4* __restrict__ dst4) {
    int i = blockIdx.x * blockDim.x + threadIdx.x;
    if (i < Ee / 4) {
        int4 d = __ldg(&dst4[i]);
        atomicAdd(&g_deg[d.x], 1);
        atomicAdd(&g_deg[d.y], 1);
        atomicAdd(&g_deg[d.z], 1);
        atomicAdd(&g_deg[d.w], 1);
    }
}

// ---------------- block-local scan ----------------
__global__ void k_scan_a() {
    __shared__ int sh[SCAN_BLK];
    int t = threadIdx.x;
    int i = blockIdx.x * SCAN_BLK + t;
    int v = (i < Nn) ? g_deg[i] : 0;
    sh[t] = v;
    __syncthreads();
    for (int off = 1; off < SCAN_BLK; off <<= 1) {
        int x = (t >= off) ? sh[t - off] : 0;
        __syncthreads();
        sh[t] += x;
        __syncthreads();
    }
    if (i < Nn) g_rowptr[i] = sh[t] - v;
    if (t == SCAN_BLK - 1) g_blocksums[blockIdx.x] = sh[t];
}

// ---------------- fused: scan finalize + wq + cnt init + error + reductions ----------------
__global__ void k_scanbc_error(const float* __restrict__ ys, const float* __restrict__ yt,
                               const void* __restrict__ mask) {
    int t = threadIdx.x;
    int b = blockIdx.x;

    if (b < GN) {
        __shared__ int sh[128];
        if (t < 128) sh[t] = (t < SCAN_NBLK) ? g_blocksums[t] : 0;
        __syncthreads();
        for (int off = 1; off < 128; off <<= 1) {
            int x = (t >= off && t < 128) ? sh[t - off] : 0;
            __syncthreads();
            if (t < 128) sh[t] += x;
            __syncthreads();
        }
        int i = b * 256 + t;
        if (i < Nn) {
            int blk = i >> 10;
            int add = blk ? sh[blk - 1] : 0;
            int rp = g_rowptr[i] + add;
            g_rowptr[i] = rp;
            g_cnt[i] = rp;                    // fill's running cursor
            int d = g_deg[i]; if (d < 1) d = 1;
            g_wq[i] = (int)(rsqrtf((float)d) * 32767.f + 0.5f);
        }
        if (i == 0) g_rowptr[Nn] = Ee;
        __syncthreads();
    }

    // error: thread handles node n = idx>>3, 8 channels (y-form fp16)
    int idx = b * 256 + t;
    float a = 0.f, cm = 0.f;
    if (idx < Nn * 8) {
        int n = idx >> 3;
        float m = mask_at(mask, n) ? 1.f : 0.f;
        const float4* pys = (const float4*)ys + idx * 2;
        const float4* pyt = (const float4*)yt + idx * 2;
        float4 s0 = __ldg(pys), s1 = __ldg(pys + 1);
        float4 t0 = __ldg(pyt), t1 = __ldg(pyt + 1);
        float e0 = m * (t0.x - s0.x), e1 = m * (t0.y - s0.y);
        float e2 = m * (t0.z - s0.z), e3 = m * (t0.w - s0.w);
        float e4 = m * (t1.x - s1.x), e5 = m * (t1.y - s1.y);
        float e6 = m * (t1.z - s1.z), e7 = m * (t1.w - s1.w);
        a = fabsf(e0) + fabsf(e1) + fabsf(e2) + fabsf(e3)
          + fabsf(e4) + fabsf(e5) + fabsf(e6) + fabsf(e7);
        uint4 hz, hl;
        *(__half2*)&hz.x = __floats2half2_rn(e0, e1);
        *(__half2*)&hz.y = __floats2half2_rn(e2, e3);
        *(__half2*)&hz.z = __floats2half2_rn(e4, e5);
        *(__half2*)&hz.w = __floats2half2_rn(e6, e7);
        float lc = 1.f - AC;
        *(__half2*)&hl.x = __floats2half2_rn(lc * e0, lc * e1);
        *(__half2*)&hl.y = __floats2half2_rn(lc * e2, lc * e3);
        *(__half2*)&hl.z = __floats2half2_rn(lc * e4, lc * e5);
        *(__half2*)&hl.w = __floats2half2_rn(lc * e6, lc * e7);
        g_hA[idx]    = hz;
        g_lasth[idx] = hl;
        if ((idx & 7) == 0) cm = m;
    }
    for (int o = 16; o; o >>= 1) {
        a  += __shfl_down_sync(0xffffffffu, a, o);
        cm += __shfl_down_sync(0xffffffffu, cm, o);
    }
    __shared__ float sa[8], sc[8];
    int warp = t >> 5, lane = t & 31;
    if (lane == 0) { sa[warp] = a; sc[warp] = cm; }
    __syncthreads();
    if (t == 0) {
        float ta = 0.f, tc = 0.f;
        for (int w = 0; w < 8; w++) { ta += sa[w]; tc += sc[w]; }
        atomicAdd(&g_sumabs, ta);
        atomicAdd(&g_nummask, tc);
    }
}

// ---------------- CSR fill: 1 edge/thread, single atomic cursor ----------------
__global__ void k_fill(const int* __restrict__ src, const int* __restrict__ dst) {
    int i = blockIdx.x * blockDim.x + threadIdx.x;
    if (i >= Ee) return;
    int d = dst[i];
    int s = src[i];
    int pos = atomicAdd(&g_cnt[d], 1);
    g_csr[pos] = ((unsigned)g_wq[s] << 17) | (unsigned)s;
}

// ---------------- propagation layer (proven core) ----------------
__global__ void k_prop16(const uint4* __restrict__ yin, uint4* __restrict__ yout,
                         float* __restrict__ out_f,
                         const uint4* __restrict__ last, float alpha, float lo, float hi) {
    int w = (blockIdx.x * blockDim.x + threadIdx.x) >> 5;
    int lane = threadIdx.x & 31;
    if (w >= Nn) return;
    int grp = lane >> 3;
    int k   = lane & 7;

    int s0 = g_rowptr[w];
    int nE = g_rowptr[w + 1] - s0;

    float acc0 = 0.f, acc1 = 0.f, acc2 = 0.f, acc3 = 0.f;
    float acc4 = 0.f, acc5 = 0.f, acc6 = 0.f, acc7 = 0.f;

    for (int base = 0; base < nE; base += 32) {
        unsigned packed = 0;
        if (base + lane < nE) packed = __ldg(&g_csr[s0 + base + lane]);
        int cnt = nE - base;
        if (cnt > 32) cnt = 32;
        for (int j = 0; j < cnt; j += 4) {
            unsigned p = __shfl_sync(0xffffffffu, packed, j + grp);
            int   ss = (int)(p & 0x1FFFFu);
            float ww = (float)(p >> 17);
            uint4 h = __ldg(yin + (size_t)ss * 8 + k);
            float2 v0 = __half22float2(*(const __half2*)&h.x);
            float2 v1 = __half22float2(*(const __half2*)&h.y);
            float2 v2 = __half22float2(*(const __half2*)&h.z);
            float2 v3 = __half22float2(*(const __half2*)&h.w);
            acc0 = fmaf(ww, v0.x, acc0);
            acc1 = fmaf(ww, v0.y, acc1);
            acc2 = fmaf(ww, v1.x, acc2);
            acc3 = fmaf(ww, v1.y, acc3);
            acc4 = fmaf(ww, v2.x, acc4);
            acc5 = fmaf(ww, v2.y, acc5);
            acc6 = fmaf(ww, v3.x, acc6);
            acc7 = fmaf(ww, v3.y, acc7);
        }
    }

#pragma unroll
    for (int o = 8; o <= 16; o <<= 1) {
        acc0 += __shfl_xor_sync(0xffffffffu, acc0, o);
        acc1 += __shfl_xor_sync(0xffffffffu, acc1, o);
        acc2 += __shfl_xor_sync(0xffffffffu, acc2, o);
        acc3 += __shfl_xor_sync(0xffffffffu, acc3, o);
        acc4 += __shfl_xor_sync(0xffffffffu, acc4, o);
        acc5 += __shfl_xor_sync(0xffffffffu, acc5, o);
        acc6 += __shfl_xor_sync(0xffffffffu, acc6, o);
        acc7 += __shfl_xor_sync(0xffffffffu, acc7, o);
    }

    if (grp == 0) {
        float nd = rsqrtf((float)(nE < 1 ? 1 : nE));
        float sc = alpha * nd * (1.0f / 32767.0f);
        uint4 lh = __ldg(last + (size_t)w * 8 + k);
        float2 l0 = __half22float2(*(const __half2*)&lh.x);
        float2 l1 = __half22float2(*(const __half2*)&lh.y);
        float2 l2 = __half22float2(*(const __half2*)&lh.z);
        float2 l3 = __half22float2(*(const __half2*)&lh.w);
        float o0 = fminf(fmaxf(fmaf(sc, acc0, l0.x), lo), hi);
        float o1 = fminf(fmaxf(fmaf(sc, acc1, l0.y), lo), hi);
        float o2 = fminf(fmaxf(fmaf(sc, acc2, l1.x), lo), hi);
        float o3 = fminf(fmaxf(fmaf(sc, acc3, l1.y), lo), hi);
        float o4 = fminf(fmaxf(fmaf(sc, acc4, l2.x), lo), hi);
        float o5 = fminf(fmaxf(fmaf(sc, acc5, l2.y), lo), hi);
        float o6 = fminf(fmaxf(fmaf(sc, acc6, l3.x), lo), hi);
        float o7 = fminf(fmaxf(fmaf(sc, acc7, l3.y), lo), hi);
        if (out_f) {
            float* op = out_f + (size_t)w * Cc + 8 * k;
            *(float4*)(op)     = make_float4(o0, o1, o2, o3);
            *(float4*)(op + 4) = make_float4(o4, o5, o6, o7);
        } else {
            uint4 hout;
            *(__half2*)&hout.x = __floats2half2_rn(o0, o1);
            *(__half2*)&hout.y = __floats2half2_rn(o2, o3);
            *(__half2*)&hout.z = __floats2half2_rn(o4, o5);
            *(__half2*)&hout.w = __floats2half2_rn(o6, o7);
            yout[(size_t)w * 8 + k] = hout;
        }
    }
}

// ---------------- final correct layer fused with combine ----------------
// Computes smoothed_error (clip [-1,1]), per-node scale, blends with y_soft/y_true,
// writes y (fp16) to yout and (1-AS)*y to lasth.
__global__ void k_prop_combine(const uint4* __restrict__ yin, uint4* __restrict__ yout,
                               uint4* __restrict__ lasth,
                               const uint4* __restrict__ last,
                               const float* __restrict__ ys, const float* __restrict__ yt,
                               const void* __restrict__ mask) {
    int w = (blockIdx.x * blockDim.x + threadIdx.x) >> 5;
    int lane = threadIdx.x & 31;
    if (w >= Nn) return;
    int grp = lane >> 3;
    int k   = lane & 7;

    int s0 = g_rowptr[w];
    int nE = g_rowptr[w + 1] - s0;

    float acc0 = 0.f, acc1 = 0.f, acc2 = 0.f, acc3 = 0.f;
    float acc4 = 0.f, acc5 = 0.f, acc6 = 0.f, acc7 = 0.f;

    for (int base = 0; base < nE; base += 32) {
        unsigned packed = 0;
        if (base + lane < nE) packed = __ldg(&g_csr[s0 + base + lane]);
        int cnt = nE - base;
        if (cnt > 32) cnt = 32;
        for (int j = 0; j < cnt; j += 4) {
            unsigned p = __shfl_sync(0xffffffffu, packed, j + grp);
            int   ss = (int)(p & 0x1FFFFu);
            float ww = (float)(p >> 17);
            uint4 h = __ldg(yin + (size_t)ss * 8 + k);
            float2 v0 = __half22float2(*(const __half2*)&h.x);
            float2 v1 = __half22float2(*(const __half2*)&h.y);
            float2 v2 = __half22float2(*(const __half2*)&h.z);
            float2 v3 = __half22float2(*(const __half2*)&h.w);
            acc0 = fmaf(ww, v0.x, acc0);
            acc1 = fmaf(ww, v0.y, acc1);
            acc2 = fmaf(ww, v1.x, acc2);
            acc3 = fmaf(ww, v1.y, acc3);
            acc4 = fmaf(ww, v2.x, acc4);
            acc5 = fmaf(ww, v2.y, acc5);
            acc6 = fmaf(ww, v3.x, acc6);
            acc7 = fmaf(ww, v3.y, acc7);
        }
    }

#pragma unroll
    for (int o = 8; o <= 16; o <<= 1) {
        acc0 += __shfl_xor_sync(0xffffffffu, acc0, o);
        acc1 += __shfl_xor_sync(0xffffffffu, acc1, o);
        acc2 += __shfl_xor_sync(0xffffffffu, acc2, o);
        acc3 += __shfl_xor_sync(0xffffffffu, acc3, o);
        acc4 += __shfl_xor_sync(0xffffffffu, acc4, o);
        acc5 += __shfl_xor_sync(0xffffffffu, acc5, o);
        acc6 += __shfl_xor_sync(0xffffffffu, acc6, o);
        acc7 += __shfl_xor_sync(0xffffffffu, acc7, o);
    }

    if (grp == 0) {   // lanes 0..7 converged; hold all 64 channels
        float nd = rsqrtf((float)(nE < 1 ? 1 : nE));
        float sc = AC * nd * (1.0f / 32767.0f);
        uint4 lh = __ldg(last + (size_t)w * 8 + k);
        float2 l0 = __half22float2(*(const __half2*)&lh.x);
        float2 l1 = __half22float2(*(const __half2*)&lh.y);
        float2 l2 = __half22float2(*(const __half2*)&lh.z);
        float2 l3 = __half22float2(*(const __half2*)&lh.w);
        float e0 = fminf(fmaxf(fmaf(sc, acc0, l0.x), -1.f), 1.f);
        float e1 = fminf(fmaxf(fmaf(sc, acc1, l0.y), -1.f), 1.f);
        float e2 = fminf(fmaxf(fmaf(sc, acc2, l1.x), -1.f), 1.f);
        float e3 = fminf(fmaxf(fmaf(sc, acc3, l1.y), -1.f), 1.f);
        float e4 = fminf(fmaxf(fmaf(sc, acc4, l2.x), -1.f), 1.f);
        float e5 = fminf(fmaxf(fmaf(sc, acc5, l2.y), -1.f), 1.f);
        float e6 = fminf(fmaxf(fmaf(sc, acc6, l3.x), -1.f), 1.f);
        float e7 = fminf(fmaxf(fmaf(sc, acc7, l3.y), -1.f), 1.f);

        // per-node sum of |smoothed_error| over all 64 channels (8 lanes x 8)
        float part = fabsf(e0) + fabsf(e1) + fabsf(e2) + fabsf(e3)
                   + fabsf(e4) + fabsf(e5) + fabsf(e6) + fabsf(e7);
        part += __shfl_xor_sync(0xFFu, part, 1);
        part += __shfl_xor_sync(0xFFu, part, 2);
        part += __shfl_xor_sync(0xFFu, part, 4);

        float sigma = g_sumabs / g_nummask;
        float scale = sigma / part;
        if (isinf(scale) || scale > 1000.f) scale = 1.f;

        const float4* pys = (const float4*)(ys + (size_t)w * Cc + 8 * k);
        const float4* pyt = (const float4*)(yt + (size_t)w * Cc + 8 * k);
        float4 sA = __ldg(pys), sB = __ldg(pys + 1);
        float4 tA = __ldg(pyt), tB = __ldg(pyt + 1);

        float r0 = sA.x + scale * e0; if (isnan(r0)) r0 = sA.x;
        float r1 = sA.y + scale * e1; if (isnan(r1)) r1 = sA.y;
        float r2 = sA.z + scale * e2; if (isnan(r2)) r2 = sA.z;
        float r3 = sA.w + scale * e3; if (isnan(r3)) r3 = sA.w;
        float r4 = sB.x + scale * e4; if (isnan(r4)) r4 = sB.x;
        float r5 = sB.y + scale * e5; if (isnan(r5)) r5 = sB.y;
        float r6 = sB.z + scale * e6; if (isnan(r6)) r6 = sB.z;
        float r7 = sB.w + scale * e7; if (isnan(r7)) r7 = sB.w;
        if (mask_at(mask, w)) {
            r0 = tA.x; r1 = tA.y; r2 = tA.z; r3 = tA.w;
            r4 = tB.x; r5 = tB.y; r6 = tB.z; r7 = tB.w;
        }
        uint4 hy, hl2;
        *(__half2*)&hy.x = __floats2half2_rn(r0, r1);
        *(__half2*)&hy.y = __floats2half2_rn(r2, r3);
        *(__half2*)&hy.z = __floats2half2_rn(r4, r5);
        *(__half2*)&hy.w = __floats2half2_rn(r6, r7);
        float ls = 1.f - AS;
        *(__half2*)&hl2.x = __floats2half2_rn(ls * r0, ls * r1);
        *(__half2*)&hl2.y = __floats2half2_rn(ls * r2, ls * r3);
        *(__half2*)&hl2.z = __floats2half2_rn(ls * r4, ls * r5);
        *(__half2*)&hl2.w = __floats2half2_rn(ls * r6, ls * r7);
        yout[(size_t)w * 8 + k]  = hy;
        lasth[(size_t)w * 8 + k] = hl2;
    }
}

// ---------------- launch ----------------
extern "C" void kernel_launch(void* const* d_in, const int* in_sizes, int n_in,
                              void* d_out, int out_size) {
    const float* y_soft = (const float*)d_in[0];
    const float* y_true = (const float*)d_in[1];
    const int*   src    = (const int*)d_in[2];
    const int*   dst    = (const int*)d_in[3];
    const void*  mask   = (const void*)d_in[4];
    float* out = (float*)d_out;

    const int T = 256;
    const int gE  = (Ee + T - 1) / T;
    const int gE4 = (Ee / 4 + T - 1) / T;
    const int gS  = Nn * 8 / T;              // 3125
    const int gW  = (Nn * 32 + T - 1) / T;   // warp per node

    uint4 *hA, *hB, *lasth;
    cudaGetSymbolAddress((void**)&hA, g_hA);
    cudaGetSymbolAddress((void**)&hB, g_hB);
    cudaGetSymbolAddress((void**)&lasth, g_lasth);

    // preprocessing
    k_init<<<GN, T>>>(mask);
    k_hist<<<gE4, T>>>((const int4*)dst);
    k_scan_a<<<SCAN_NBLK, SCAN_BLK>>>();
    k_scanbc_error<<<gS, T>>>(y_soft, y_true, mask);
    k_fill<<<gE, T>>>(src, dst);

    // correct phase: 9 plain layers + fused 10th(+combine)
    // hA -> hB -> hA ... ; after 9 layers state is in hB
    {
        uint4* in = hA; uint4* outp = hB;
        for (int l = 0; l < 9; l++) {
            k_prop16<<<gW, T>>>(in, outp, (float*)0, lasth, AC, -1.f, 1.f);
            uint4* t = in; in = outp; outp = t;
        }
        // in == hB: fused final correct layer + combine -> writes y into hA, lasth
        k_prop_combine<<<gW, T>>>(in, hA, lasth, lasth, y_soft, y_true, mask);
    }

    // smooth phase: 10 layers from hA, final writes fp32 to d_out
    {
        uint4* in = hA; uint4* outp = hB;
        for (int l = 0; l < 9; l++) {
            k_prop16<<<gW, T>>>(in, outp, (float*)0, lasth, AS, 0.f, 1.f);
            uint4* t = in; in = outp; outp = t;
        }
        k_prop16<<<gW, T>>>(in, (uint4*)0, out, lasth, AS, 0.f, 1.f);
    }
    (void)in_sizes; (void)n_in; (void)out_size;
}

// round 10
// speedup vs baseline: 1.5455x; 1.5455x over previous
#include <cuda_runtime.h>
#include <cuda_fp16.h>
#include <math.h>

#define Nn 100000
#define Ee 3200000
#define Cc 64
#define AC 0.979f
#define AS 0.756f
#define SCAN_BLK 1024
#define SCAN_NBLK ((Nn + SCAN_BLK - 1) / SCAN_BLK)   // 98
#define GN ((Nn + 255) / 256)                        // 391

// ---------------- static scratch ----------------
__device__ uint4    g_hA[Nn * 8];      // fp16 state rows: 64 halfs = 128B = 8 uint4
__device__ uint4    g_hB[Nn * 8];
__device__ uint4    g_lasth[Nn * 8];
__device__ int      g_deg[Nn];
__device__ int      g_cnt[Nn];         // pre-initialized to rowptr; fill bumps it
__device__ int      g_rowptr[Nn + 1];
__device__ int      g_wq[Nn];          // 15-bit quantized norm per node
__device__ unsigned g_csr[Ee];         // (wq<<17) | src  — 4B per edge
__device__ int      g_blocksums[128];
__device__ float    g_sumabs;
__device__ float    g_nummask;
__device__ int      g_mask_mode;       // 0=uint8, 1=int32, 2=float32

__device__ __forceinline__ bool mask_at(const void* __restrict__ mp, int i) {
    int mode = g_mask_mode;
    if (mode == 1) return ((const int*)mp)[i] != 0;
    if (mode == 2) return ((const float*)mp)[i] != 0.0f;
    return ((const unsigned char*)mp)[i] != 0;
}

// ---------------- init + mask dtype detection ----------------
__global__ void k_init(const void* __restrict__ mp) {
    int i = blockIdx.x * blockDim.x + threadIdx.x;
    if (i < Nn) g_deg[i] = 0;
    if (i == 0) { g_sumabs = 0.f; g_nummask = 0.f; }
    if (blockIdx.x == 0) {
        __shared__ int s_iok, s_fok;
        if (threadIdx.x == 0) { s_iok = 1; s_fok = 1; }
        __syncthreads();
        const int*   ip = (const int*)mp;
        const float* fp = (const float*)mp;
        bool iok = true, fok = true;
        for (int j = threadIdx.x; j < 1024; j += 256) {
            int v = ip[j];
            if (v != 0 && v != 1) iok = false;
            float f = fp[j];
            if (!(f == 0.0f || f == 1.0f)) fok = false;
        }
        if (!iok) s_iok = 0;
        if (!fok) s_fok = 0;
        __syncthreads();
        if (threadIdx.x == 0) g_mask_mode = s_iok ? 1 : (s_fok ? 2 : 0);
    }
}

// ---------------- degree histogram (4 edges / thread) ----------------
__global__ void k_hist(const int4* __restrict__ dst4) {
    int i = blockIdx.x * blockDim.x + threadIdx.x;
    if (i < Ee / 4) {
        int4 d = __ldg(&dst4[i]);
        atomicAdd(&g_deg[d.x], 1);
        atomicAdd(&g_deg[d.y], 1);
        atomicAdd(&g_deg[d.z], 1);
        atomicAdd(&g_deg[d.w], 1);
    }
}

// ---------------- block-local scan ----------------
__global__ void k_scan_a() {
    __shared__ int sh[SCAN_BLK];
    int t = threadIdx.x;
    int i = blockIdx.x * SCAN_BLK + t;
    int v = (i < Nn) ? g_deg[i] : 0;
    sh[t] = v;
    __syncthreads();
    for (int off = 1; off < SCAN_BLK; off <<= 1) {
        int x = (t >= off) ? sh[t - off] : 0;
        __syncthreads();
        sh[t] += x;
        __syncthreads();
    }
    if (i < Nn) g_rowptr[i] = sh[t] - v;
    if (t == SCAN_BLK - 1) g_blocksums[blockIdx.x] = sh[t];
}

// ---------------- fused: scan finalize + wq + cnt init + error + reductions ----------------
__global__ void k_scanbc_error(const float* __restrict__ ys, const float* __restrict__ yt,
                               const void* __restrict__ mask) {
    int t = threadIdx.x;
    int b = blockIdx.x;

    if (b < GN) {
        __shared__ int sh[128];
        if (t < 128) sh[t] = (t < SCAN_NBLK) ? g_blocksums[t] : 0;
        __syncthreads();
        for (int off = 1; off < 128; off <<= 1) {
            int x = (t >= off && t < 128) ? sh[t - off] : 0;
            __syncthreads();
            if (t < 128) sh[t] += x;
            __syncthreads();
        }
        int i = b * 256 + t;
        if (i < Nn) {
            int blk = i >> 10;
            int add = blk ? sh[blk - 1] : 0;
            int rp = g_rowptr[i] + add;
            g_rowptr[i] = rp;
            g_cnt[i] = rp;                    // fill's running cursor
            int d = g_deg[i]; if (d < 1) d = 1;
            g_wq[i] = (int)(rsqrtf((float)d) * 32767.f + 0.5f);
        }
        if (i == 0) g_rowptr[Nn] = Ee;
        __syncthreads();
    }

    // error: thread handles node n = idx>>3, 8 channels (y-form fp16)
    int idx = b * 256 + t;
    float a = 0.f, cm = 0.f;
    if (idx < Nn * 8) {
        int n = idx >> 3;
        float m = mask_at(mask, n) ? 1.f : 0.f;
        const float4* pys = (const float4*)ys + idx * 2;
        const float4* pyt = (const float4*)yt + idx * 2;
        float4 s0 = __ldg(pys), s1 = __ldg(pys + 1);
        float4 t0 = __ldg(pyt), t1 = __ldg(pyt + 1);
        float e0 = m * (t0.x - s0.x), e1 = m * (t0.y - s0.y);
        float e2 = m * (t0.z - s0.z), e3 = m * (t0.w - s0.w);
        float e4 = m * (t1.x - s1.x), e5 = m * (t1.y - s1.y);
        float e6 = m * (t1.z - s1.z), e7 = m * (t1.w - s1.w);
        a = fabsf(e0) + fabsf(e1) + fabsf(e2) + fabsf(e3)
          + fabsf(e4) + fabsf(e5) + fabsf(e6) + fabsf(e7);
        uint4 hz, hl;
        *(__half2*)&hz.x = __floats2half2_rn(e0, e1);
        *(__half2*)&hz.y = __floats2half2_rn(e2, e3);
        *(__half2*)&hz.z = __floats2half2_rn(e4, e5);
        *(__half2*)&hz.w = __floats2half2_rn(e6, e7);
        float lc = 1.f - AC;
        *(__half2*)&hl.x = __floats2half2_rn(lc * e0, lc * e1);
        *(__half2*)&hl.y = __floats2half2_rn(lc * e2, lc * e3);
        *(__half2*)&hl.z = __floats2half2_rn(lc * e4, lc * e5);
        *(__half2*)&hl.w = __floats2half2_rn(lc * e6, lc * e7);
        g_hA[idx]    = hz;
        g_lasth[idx] = hl;
        if ((idx & 7) == 0) cm = m;
    }
    for (int o = 16; o; o >>= 1) {
        a  += __shfl_down_sync(0xffffffffu, a, o);
        cm += __shfl_down_sync(0xffffffffu, cm, o);
    }
    __shared__ float sa[8], sc[8];
    int warp = t >> 5, lane = t & 31;
    if (lane == 0) { sa[warp] = a; sc[warp] = cm; }
    __syncthreads();
    if (t == 0) {
        float ta = 0.f, tc = 0.f;
        for (int w = 0; w < 8; w++) { ta += sa[w]; tc += sc[w]; }
        atomicAdd(&g_sumabs, ta);
        atomicAdd(&g_nummask, tc);
    }
}

// ---------------- CSR fill: 1 edge/thread, single atomic cursor ----------------
__global__ void k_fill(const int* __restrict__ src, const int* __restrict__ dst) {
    int i = blockIdx.x * blockDim.x + threadIdx.x;
    if (i >= Ee) return;
    int d = dst[i];
    int s = src[i];
    int pos = atomicAdd(&g_cnt[d], 1);
    g_csr[pos] = ((unsigned)g_wq[s] << 17) | (unsigned)s;
}

// ---------------- propagation layer (proven core) ----------------
__global__ void k_prop16(const uint4* __restrict__ yin, uint4* __restrict__ yout,
                         float* __restrict__ out_f,
                         const uint4* __restrict__ last, float alpha, float lo, float hi) {
    int w = (blockIdx.x * blockDim.x + threadIdx.x) >> 5;
    int lane = threadIdx.x & 31;
    if (w >= Nn) return;
    int grp = lane >> 3;
    int k   = lane & 7;

    int s0 = g_rowptr[w];
    int nE = g_rowptr[w + 1] - s0;

    float acc0 = 0.f, acc1 = 0.f, acc2 = 0.f, acc3 = 0.f;
    float acc4 = 0.f, acc5 = 0.f, acc6 = 0.f, acc7 = 0.f;

    for (int base = 0; base < nE; base += 32) {
        unsigned packed = 0;
        if (base + lane < nE) packed = __ldg(&g_csr[s0 + base + lane]);
        int cnt = nE - base;
        if (cnt > 32) cnt = 32;
        for (int j = 0; j < cnt; j += 4) {
            unsigned p = __shfl_sync(0xffffffffu, packed, j + grp);
            int   ss = (int)(p & 0x1FFFFu);
            float ww = (float)(p >> 17);
            uint4 h = __ldg(yin + (size_t)ss * 8 + k);
            float2 v0 = __half22float2(*(const __half2*)&h.x);
            float2 v1 = __half22float2(*(const __half2*)&h.y);
            float2 v2 = __half22float2(*(const __half2*)&h.z);
            float2 v3 = __half22float2(*(const __half2*)&h.w);
            acc0 = fmaf(ww, v0.x, acc0);
            acc1 = fmaf(ww, v0.y, acc1);
            acc2 = fmaf(ww, v1.x, acc2);
            acc3 = fmaf(ww, v1.y, acc3);
            acc4 = fmaf(ww, v2.x, acc4);
            acc5 = fmaf(ww, v2.y, acc5);
            acc6 = fmaf(ww, v3.x, acc6);
            acc7 = fmaf(ww, v3.y, acc7);
        }
    }

#pragma unroll
    for (int o = 8; o <= 16; o <<= 1) {
        acc0 += __shfl_xor_sync(0xffffffffu, acc0, o);
        acc1 += __shfl_xor_sync(0xffffffffu, acc1, o);
        acc2 += __shfl_xor_sync(0xffffffffu, acc2, o);
        acc3 += __shfl_xor_sync(0xffffffffu, acc3, o);
        acc4 += __shfl_xor_sync(0xffffffffu, acc4, o);
        acc5 += __shfl_xor_sync(0xffffffffu, acc5, o);
        acc6 += __shfl_xor_sync(0xffffffffu, acc6, o);
        acc7 += __shfl_xor_sync(0xffffffffu, acc7, o);
    }

    if (grp == 0) {
        float nd = rsqrtf((float)(nE < 1 ? 1 : nE));
        float sc = alpha * nd * (1.0f / 32767.0f);
        uint4 lh = __ldg(last + (size_t)w * 8 + k);
        float2 l0 = __half22float2(*(const __half2*)&lh.x);
        float2 l1 = __half22float2(*(const __half2*)&lh.y);
        float2 l2 = __half22float2(*(const __half2*)&lh.z);
        float2 l3 = __half22float2(*(const __half2*)&lh.w);
        float o0 = fminf(fmaxf(fmaf(sc, acc0, l0.x), lo), hi);
        float o1 = fminf(fmaxf(fmaf(sc, acc1, l0.y), lo), hi);
        float o2 = fminf(fmaxf(fmaf(sc, acc2, l1.x), lo), hi);
        float o3 = fminf(fmaxf(fmaf(sc, acc3, l1.y), lo), hi);
        float o4 = fminf(fmaxf(fmaf(sc, acc4, l2.x), lo), hi);
        float o5 = fminf(fmaxf(fmaf(sc, acc5, l2.y), lo), hi);
        float o6 = fminf(fmaxf(fmaf(sc, acc6, l3.x), lo), hi);
        float o7 = fminf(fmaxf(fmaf(sc, acc7, l3.y), lo), hi);
        if (out_f) {
            float* op = out_f + (size_t)w * Cc + 8 * k;
            *(float4*)(op)     = make_float4(o0, o1, o2, o3);
            *(float4*)(op + 4) = make_float4(o4, o5, o6, o7);
        } else {
            uint4 hout;
            *(__half2*)&hout.x = __floats2half2_rn(o0, o1);
            *(__half2*)&hout.y = __floats2half2_rn(o2, o3);
            *(__half2*)&hout.z = __floats2half2_rn(o4, o5);
            *(__half2*)&hout.w = __floats2half2_rn(o6, o7);
            yout[(size_t)w * 8 + k] = hout;
        }
    }
}

// ---------------- final correct layer fused with combine ----------------
__global__ void k_prop_combine(const uint4* __restrict__ yin, uint4* __restrict__ yout,
                               uint4* __restrict__ lasth,
                               const uint4* __restrict__ last,
                               const float* __restrict__ ys, const float* __restrict__ yt,
                               const void* __restrict__ mask) {
    int w = (blockIdx.x * blockDim.x + threadIdx.x) >> 5;
    int lane = threadIdx.x & 31;
    if (w >= Nn) return;
    int grp = lane >> 3;
    int k   = lane & 7;

    int s0 = g_rowptr[w];
    int nE = g_rowptr[w + 1] - s0;

    float acc0 = 0.f, acc1 = 0.f, acc2 = 0.f, acc3 = 0.f;
    float acc4 = 0.f, acc5 = 0.f, acc6 = 0.f, acc7 = 0.f;

    for (int base = 0; base < nE; base += 32) {
        unsigned packed = 0;
        if (base + lane < nE) packed = __ldg(&g_csr[s0 + base + lane]);
        int cnt = nE - base;
        if (cnt > 32) cnt = 32;
        for (int j = 0; j < cnt; j += 4) {
            unsigned p = __shfl_sync(0xffffffffu, packed, j + grp);
            int   ss = (int)(p & 0x1FFFFu);
            float ww = (float)(p >> 17);
            uint4 h = __ldg(yin + (size_t)ss * 8 + k);
            float2 v0 = __half22float2(*(const __half2*)&h.x);
            float2 v1 = __half22float2(*(const __half2*)&h.y);
            float2 v2 = __half22float2(*(const __half2*)&h.z);
            float2 v3 = __half22float2(*(const __half2*)&h.w);
            acc0 = fmaf(ww, v0.x, acc0);
            acc1 = fmaf(ww, v0.y, acc1);
            acc2 = fmaf(ww, v1.x, acc2);
            acc3 = fmaf(ww, v1.y, acc3);
            acc4 = fmaf(ww, v2.x, acc4);
            acc5 = fmaf(ww, v2.y, acc5);
            acc6 = fmaf(ww, v3.x, acc6);
            acc7 = fmaf(ww, v3.y, acc7);
        }
    }

#pragma unroll
    for (int o = 8; o <= 16; o <<= 1) {
        acc0 += __shfl_xor_sync(0xffffffffu, acc0, o);
        acc1 += __shfl_xor_sync(0xffffffffu, acc1, o);
        acc2 += __shfl_xor_sync(0xffffffffu, acc2, o);
        acc3 += __shfl_xor_sync(0xffffffffu, acc3, o);
        acc4 += __shfl_xor_sync(0xffffffffu, acc4, o);
        acc5 += __shfl_xor_sync(0xffffffffu, acc5, o);
        acc6 += __shfl_xor_sync(0xffffffffu, acc6, o);
        acc7 += __shfl_xor_sync(0xffffffffu, acc7, o);
    }

    if (grp == 0) {   // lanes 0..7 converged; hold all 64 channels
        float nd = rsqrtf((float)(nE < 1 ? 1 : nE));
        float sc = AC * nd * (1.0f / 32767.0f);
        uint4 lh = __ldg(last + (size_t)w * 8 + k);
        float2 l0 = __half22float2(*(const __half2*)&lh.x);
        float2 l1 = __half22float2(*(const __half2*)&lh.y);
        float2 l2 = __half22float2(*(const __half2*)&lh.z);
        float2 l3 = __half22float2(*(const __half2*)&lh.w);
        float e0 = fminf(fmaxf(fmaf(sc, acc0, l0.x), -1.f), 1.f);
        float e1 = fminf(fmaxf(fmaf(sc, acc1, l0.y), -1.f), 1.f);
        float e2 = fminf(fmaxf(fmaf(sc, acc2, l1.x), -1.f), 1.f);
        float e3 = fminf(fmaxf(fmaf(sc, acc3, l1.y), -1.f), 1.f);
        float e4 = fminf(fmaxf(fmaf(sc, acc4, l2.x), -1.f), 1.f);
        float e5 = fminf(fmaxf(fmaf(sc, acc5, l2.y), -1.f), 1.f);
        float e6 = fminf(fmaxf(fmaf(sc, acc6, l3.x), -1.f), 1.f);
        float e7 = fminf(fmaxf(fmaf(sc, acc7, l3.y), -1.f), 1.f);

        float part = fabsf(e0) + fabsf(e1) + fabsf(e2) + fabsf(e3)
                   + fabsf(e4) + fabsf(e5) + fabsf(e6) + fabsf(e7);
        part += __shfl_xor_sync(0xFFu, part, 1);
        part += __shfl_xor_sync(0xFFu, part, 2);
        part += __shfl_xor_sync(0xFFu, part, 4);

        float sigma = g_sumabs / g_nummask;
        float scale = sigma / part;
        if (isinf(scale) || scale > 1000.f) scale = 1.f;

        const float4* pys = (const float4*)(ys + (size_t)w * Cc + 8 * k);
        const float4* pyt = (const float4*)(yt + (size_t)w * Cc + 8 * k);
        float4 sA = __ldg(pys), sB = __ldg(pys + 1);
        float4 tA = __ldg(pyt), tB = __ldg(pyt + 1);

        float r0 = sA.x + scale * e0; if (isnan(r0)) r0 = sA.x;
        float r1 = sA.y + scale * e1; if (isnan(r1)) r1 = sA.y;
        float r2 = sA.z + scale * e2; if (isnan(r2)) r2 = sA.z;
        float r3 = sA.w + scale * e3; if (isnan(r3)) r3 = sA.w;
        float r4 = sB.x + scale * e4; if (isnan(r4)) r4 = sB.x;
        float r5 = sB.y + scale * e5; if (isnan(r5)) r5 = sB.y;
        float r6 = sB.z + scale * e6; if (isnan(r6)) r6 = sB.z;
        float r7 = sB.w + scale * e7; if (isnan(r7)) r7 = sB.w;
        if (mask_at(mask, w)) {
            r0 = tA.x; r1 = tA.y; r2 = tA.z; r3 = tA.w;
            r4 = tB.x; r5 = tB.y; r6 = tB.z; r7 = tB.w;
        }
        uint4 hy, hl2;
        *(__half2*)&hy.x = __floats2half2_rn(r0, r1);
        *(__half2*)&hy.y = __floats2half2_rn(r2, r3);
        *(__half2*)&hy.z = __floats2half2_rn(r4, r5);
        *(__half2*)&hy.w = __floats2half2_rn(r6, r7);
        float ls = 1.f - AS;
        *(__half2*)&hl2.x = __floats2half2_rn(ls * r0, ls * r1);
        *(__half2*)&hl2.y = __floats2half2_rn(ls * r2, ls * r3);
        *(__half2*)&hl2.z = __floats2half2_rn(ls * r4, ls * r5);
        *(__half2*)&hl2.w = __floats2half2_rn(ls * r6, ls * r7);
        yout[(size_t)w * 8 + k]  = hy;
        lasth[(size_t)w * 8 + k] = hl2;
    }
}

// ---------------- launch ----------------
extern "C" void kernel_launch(void* const* d_in, const int* in_sizes, int n_in,
                              void* d_out, int out_size) {
    const float* y_soft = (const float*)d_in[0];
    const float* y_true = (const float*)d_in[1];
    const int*   src    = (const int*)d_in[2];
    const int*   dst    = (const int*)d_in[3];
    const void*  mask   = (const void*)d_in[4];
    float* out = (float*)d_out;

    const int T = 256;
    const int gE  = (Ee + T - 1) / T;
    const int gE4 = (Ee / 4 + T - 1) / T;
    const int gS  = Nn * 8 / T;              // 3125
    const int gW  = (Nn * 32 + T - 1) / T;   // warp per node

    uint4 *hA, *hB, *lasth;
    cudaGetSymbolAddress((void**)&hA, g_hA);
    cudaGetSymbolAddress((void**)&hB, g_hB);
    cudaGetSymbolAddress((void**)&lasth, g_lasth);

    // preprocessing
    k_init<<<GN, T>>>(mask);
    k_hist<<<gE4, T>>>((const int4*)dst);
    k_scan_a<<<SCAN_NBLK, SCAN_BLK>>>();
    k_scanbc_error<<<gS, T>>>(y_soft, y_true, mask);
    k_fill<<<gE, T>>>(src, dst);

    // correct phase: 9 plain layers + fused 10th(+combine)
    {
        uint4* in = hA; uint4* outp = hB;
        for (int l = 0; l < 9; l++) {
            k_prop16<<<gW, T>>>(in, outp, (float*)0, lasth, AC, -1.f, 1.f);
            uint4* t = in; in = outp; outp = t;
        }
        // in == hB: fused final correct layer + combine -> writes y into hA, lasth
        k_prop_combine<<<gW, T>>>(in, hA, lasth, lasth, y_soft, y_true, mask);
    }

    // smooth phase: 10 layers from hA, final writes fp32 to d_out
    {
        uint4* in = hA; uint4* outp = hB;
        for (int l = 0; l < 9; l++) {
            k_prop16<<<gW, T>>>(in, outp, (float*)0, lasth, AS, 0.f, 1.f);
            uint4* t = in; in = outp; outp = t;
        }
        k_prop16<<<gW, T>>>(in, (uint4*)0, out, lasth, AS, 0.f, 1.f);
    }
    (void)in_sizes; (void)n_in; (void)out_size;
}

// round 11
// speedup vs baseline: 1.5614x; 1.0103x over previous
#include <cuda_runtime.h>
#include <cuda_fp16.h>
#include <math.h>

#define Nn 100000
#define Ee 3200000
#define Cc 64
#define AC 0.979f
#define AS 0.756f
#define SCAN_BLK 1024
#define SCAN_NBLK ((Nn + SCAN_BLK - 1) / SCAN_BLK)   // 98
#define GN ((Nn + 255) / 256)                        // 391

// ---------------- static scratch ----------------
__device__ uint4    g_hA[Nn * 8];      // fp16 state rows: 64 halfs = 128B = 8 uint4
__device__ uint4    g_hB[Nn * 8];
__device__ uint4    g_lasth[Nn * 8];
__device__ int      g_deg[Nn];
__device__ int      g_cnt[Nn];         // pre-initialized to rowptr; fill bumps it
__device__ int      g_rowptr[Nn + 1];
__device__ int      g_wq[Nn];          // 15-bit quantized norm per node
__device__ unsigned g_csr[Ee];         // (wq<<17) | src  — 4B per edge
__device__ int      g_blocksums[128];
__device__ float    g_sumabs;
__device__ float    g_nummask;
__device__ int      g_mask_mode;       // 0=uint8, 1=int32, 2=float32

__device__ __forceinline__ bool mask_at(const void* __restrict__ mp, int i) {
    int mode = g_mask_mode;
    if (mode == 1) return ((const int*)mp)[i] != 0;
    if (mode == 2) return ((const float*)mp)[i] != 0.0f;
    return ((const unsigned char*)mp)[i] != 0;
}

// ---------------- init + mask dtype detection ----------------
__global__ void k_init(const void* __restrict__ mp) {
    int i = blockIdx.x * blockDim.x + threadIdx.x;
    if (i < Nn) g_deg[i] = 0;
    if (i == 0) { g_sumabs = 0.f; g_nummask = 0.f; }
    if (blockIdx.x == 0) {
        __shared__ int s_iok, s_fok;
        if (threadIdx.x == 0) { s_iok = 1; s_fok = 1; }
        __syncthreads();
        const int*   ip = (const int*)mp;
        const float* fp = (const float*)mp;
        bool iok = true, fok = true;
        for (int j = threadIdx.x; j < 1024; j += 256) {
            int v = ip[j];
            if (v != 0 && v != 1) iok = false;
            float f = fp[j];
            if (!(f == 0.0f || f == 1.0f)) fok = false;
        }
        if (!iok) s_iok = 0;
        if (!fok) s_fok = 0;
        __syncthreads();
        if (threadIdx.x == 0) g_mask_mode = s_iok ? 1 : (s_fok ? 2 : 0);
    }
}

// ---------------- degree histogram (4 edges / thread) ----------------
__global__ void k_hist(const int4* __restrict__ dst4) {
    int i = blockIdx.x * blockDim.x + threadIdx.x;
    if (i < Ee / 4) {
        int4 d = __ldg(&dst4[i]);
        atomicAdd(&g_deg[d.x], 1);
        atomicAdd(&g_deg[d.y], 1);
        atomicAdd(&g_deg[d.z], 1);
        atomicAdd(&g_deg[d.w], 1);
    }
}

// ---------------- block-local scan ----------------
__global__ void k_scan_a() {
    __shared__ int sh[SCAN_BLK];
    int t = threadIdx.x;
    int i = blockIdx.x * SCAN_BLK + t;
    int v = (i < Nn) ? g_deg[i] : 0;
    sh[t] = v;
    __syncthreads();
    for (int off = 1; off < SCAN_BLK; off <<= 1) {
        int x = (t >= off) ? sh[t - off] : 0;
        __syncthreads();
        sh[t] += x;
        __syncthreads();
    }
    if (i < Nn) g_rowptr[i] = sh[t] - v;
    if (t == SCAN_BLK - 1) g_blocksums[blockIdx.x] = sh[t];
}

// ---------------- fused: scan finalize + wq + cnt init + error + reductions ----------------
__global__ void k_scanbc_error(const float* __restrict__ ys, const float* __restrict__ yt,
                               const void* __restrict__ mask) {
    int t = threadIdx.x;
    int b = blockIdx.x;

    if (b < GN) {
        __shared__ int sh[128];
        if (t < 128) sh[t] = (t < SCAN_NBLK) ? g_blocksums[t] : 0;
        __syncthreads();
        for (int off = 1; off < 128; off <<= 1) {
            int x = (t >= off && t < 128) ? sh[t - off] : 0;
            __syncthreads();
            if (t < 128) sh[t] += x;
            __syncthreads();
        }
        int i = b * 256 + t;
        if (i < Nn) {
            int blk = i >> 10;
            int add = blk ? sh[blk - 1] : 0;
            int rp = g_rowptr[i] + add;
            g_rowptr[i] = rp;
            g_cnt[i] = rp;                    // fill's running cursor
            int d = g_deg[i]; if (d < 1) d = 1;
            g_wq[i] = (int)(rsqrtf((float)d) * 32767.f + 0.5f);
        }
        if (i == 0) g_rowptr[Nn] = Ee;
        __syncthreads();
    }

    // error: thread handles node n = idx>>3, 8 channels (y-form fp16)
    int idx = b * 256 + t;
    float a = 0.f, cm = 0.f;
    if (idx < Nn * 8) {
        int n = idx >> 3;
        float m = mask_at(mask, n) ? 1.f : 0.f;
        const float4* pys = (const float4*)ys + idx * 2;
        const float4* pyt = (const float4*)yt + idx * 2;
        float4 s0 = __ldg(pys), s1 = __ldg(pys + 1);
        float4 t0 = __ldg(pyt), t1 = __ldg(pyt + 1);
        float e0 = m * (t0.x - s0.x), e1 = m * (t0.y - s0.y);
        float e2 = m * (t0.z - s0.z), e3 = m * (t0.w - s0.w);
        float e4 = m * (t1.x - s1.x), e5 = m * (t1.y - s1.y);
        float e6 = m * (t1.z - s1.z), e7 = m * (t1.w - s1.w);
        a = fabsf(e0) + fabsf(e1) + fabsf(e2) + fabsf(e3)
          + fabsf(e4) + fabsf(e5) + fabsf(e6) + fabsf(e7);
        uint4 hz, hl;
        *(__half2*)&hz.x = __floats2half2_rn(e0, e1);
        *(__half2*)&hz.y = __floats2half2_rn(e2, e3);
        *(__half2*)&hz.z = __floats2half2_rn(e4, e5);
        *(__half2*)&hz.w = __floats2half2_rn(e6, e7);
        float lc = 1.f - AC;
        *(__half2*)&hl.x = __floats2half2_rn(lc * e0, lc * e1);
        *(__half2*)&hl.y = __floats2half2_rn(lc * e2, lc * e3);
        *(__half2*)&hl.z = __floats2half2_rn(lc * e4, lc * e5);
        *(__half2*)&hl.w = __floats2half2_rn(lc * e6, lc * e7);
        g_hA[idx]    = hz;
        g_lasth[idx] = hl;
        if ((idx & 7) == 0) cm = m;
    }
    for (int o = 16; o; o >>= 1) {
        a  += __shfl_down_sync(0xffffffffu, a, o);
        cm += __shfl_down_sync(0xffffffffu, cm, o);
    }
    __shared__ float sa[8], sc[8];
    int warp = t >> 5, lane = t & 31;
    if (lane == 0) { sa[warp] = a; sc[warp] = cm; }
    __syncthreads();
    if (t == 0) {
        float ta = 0.f, tc = 0.f;
        for (int w = 0; w < 8; w++) { ta += sa[w]; tc += sc[w]; }
        atomicAdd(&g_sumabs, ta);
        atomicAdd(&g_nummask, tc);
    }
}

// ---------------- CSR fill: 1 edge/thread, single atomic cursor ----------------
__global__ void k_fill(const int* __restrict__ src, const int* __restrict__ dst) {
    int i = blockIdx.x * blockDim.x + threadIdx.x;
    if (i >= Ee) return;
    int d = dst[i];
    int s = src[i];
    int pos = atomicAdd(&g_cnt[d], 1);
    g_csr[pos] = ((unsigned)g_wq[s] << 17) | (unsigned)s;
}

// ---------------- gather macro: one 4-edge group (uniform-predicated) ----------------
#define GATHER_STEP(J)                                                        \
    if ((J) < cnt) {                                                          \
        unsigned p = __shfl_sync(0xffffffffu, packed, (J) + grp);             \
        int   ss = (int)(p & 0x1FFFFu);                                       \
        float ww = (float)(p >> 17);                                          \
        uint4 h = __ldg(yin + (size_t)ss * 8 + k);                            \
        float2 v0 = __half22float2(*(const __half2*)&h.x);                    \
        float2 v1 = __half22float2(*(const __half2*)&h.y);                    \
        float2 v2 = __half22float2(*(const __half2*)&h.z);                    \
        float2 v3 = __half22float2(*(const __half2*)&h.w);                    \
        acc0 = fmaf(ww, v0.x, acc0);                                          \
        acc1 = fmaf(ww, v0.y, acc1);                                          \
        acc2 = fmaf(ww, v1.x, acc2);                                          \
        acc3 = fmaf(ww, v1.y, acc3);                                          \
        acc4 = fmaf(ww, v2.x, acc4);                                          \
        acc5 = fmaf(ww, v2.y, acc5);                                          \
        acc6 = fmaf(ww, v3.x, acc6);                                          \
        acc7 = fmaf(ww, v3.y, acc7);                                          \
    }

#define GATHER_STRIP()                                                        \
    for (int base = 0; base < nE; base += 32) {                               \
        unsigned packed = 0;                                                  \
        if (base + lane < nE) packed = __ldg(&g_csr[s0 + base + lane]);       \
        int cnt = nE - base;                                                  \
        if (cnt > 32) cnt = 32;                                               \
        GATHER_STEP(0)  GATHER_STEP(4)  GATHER_STEP(8)  GATHER_STEP(12)       \
        GATHER_STEP(16) GATHER_STEP(20) GATHER_STEP(24) GATHER_STEP(28)       \
    }

#define CROSS_GROUP_REDUCE()                                                  \
    _Pragma("unroll")                                                         \
    for (int o = 8; o <= 16; o <<= 1) {                                       \
        acc0 += __shfl_xor_sync(0xffffffffu, acc0, o);                        \
        acc1 += __shfl_xor_sync(0xffffffffu, acc1, o);                        \
        acc2 += __shfl_xor_sync(0xffffffffu, acc2, o);                        \
        acc3 += __shfl_xor_sync(0xffffffffu, acc3, o);                        \
        acc4 += __shfl_xor_sync(0xffffffffu, acc4, o);                        \
        acc5 += __shfl_xor_sync(0xffffffffu, acc5, o);                        \
        acc6 += __shfl_xor_sync(0xffffffffu, acc6, o);                        \
        acc7 += __shfl_xor_sync(0xffffffffu, acc7, o);                        \
    }

// ---------------- propagation layer: warp per node, unrolled gather ----------------
__global__ void k_prop16(const uint4* __restrict__ yin, uint4* __restrict__ yout,
                         float* __restrict__ out_f,
                         const uint4* __restrict__ last, float alpha, float lo, float hi) {
    int w = (blockIdx.x * blockDim.x + threadIdx.x) >> 5;
    int lane = threadIdx.x & 31;
    if (w >= Nn) return;
    int grp = lane >> 3;
    int k   = lane & 7;

    int s0 = g_rowptr[w];
    int nE = g_rowptr[w + 1] - s0;

    float acc0 = 0.f, acc1 = 0.f, acc2 = 0.f, acc3 = 0.f;
    float acc4 = 0.f, acc5 = 0.f, acc6 = 0.f, acc7 = 0.f;

    GATHER_STRIP()
    CROSS_GROUP_REDUCE()

    if (grp == 0) {
        float nd = rsqrtf((float)(nE < 1 ? 1 : nE));
        float sc = alpha * nd * (1.0f / 32767.0f);
        uint4 lh = __ldg(last + (size_t)w * 8 + k);
        float2 l0 = __half22float2(*(const __half2*)&lh.x);
        float2 l1 = __half22float2(*(const __half2*)&lh.y);
        float2 l2 = __half22float2(*(const __half2*)&lh.z);
        float2 l3 = __half22float2(*(const __half2*)&lh.w);
        float o0 = fminf(fmaxf(fmaf(sc, acc0, l0.x), lo), hi);
        float o1 = fminf(fmaxf(fmaf(sc, acc1, l0.y), lo), hi);
        float o2 = fminf(fmaxf(fmaf(sc, acc2, l1.x), lo), hi);
        float o3 = fminf(fmaxf(fmaf(sc, acc3, l1.y), lo), hi);
        float o4 = fminf(fmaxf(fmaf(sc, acc4, l2.x), lo), hi);
        float o5 = fminf(fmaxf(fmaf(sc, acc5, l2.y), lo), hi);
        float o6 = fminf(fmaxf(fmaf(sc, acc6, l3.x), lo), hi);
        float o7 = fminf(fmaxf(fmaf(sc, acc7, l3.y), lo), hi);
        if (out_f) {
            float* op = out_f + (size_t)w * Cc + 8 * k;
            *(float4*)(op)     = make_float4(o0, o1, o2, o3);
            *(float4*)(op + 4) = make_float4(o4, o5, o6, o7);
        } else {
            uint4 hout;
            *(__half2*)&hout.x = __floats2half2_rn(o0, o1);
            *(__half2*)&hout.y = __floats2half2_rn(o2, o3);
            *(__half2*)&hout.z = __floats2half2_rn(o4, o5);
            *(__half2*)&hout.w = __floats2half2_rn(o6, o7);
            yout[(size_t)w * 8 + k] = hout;
        }
    }
}

// ---------------- final correct layer fused with combine ----------------
__global__ void k_prop_combine(const uint4* __restrict__ yin, uint4* __restrict__ yout,
                               uint4* __restrict__ lasth,
                               const uint4* __restrict__ last,
                               const float* __restrict__ ys, const float* __restrict__ yt,
                               const void* __restrict__ mask) {
    int w = (blockIdx.x * blockDim.x + threadIdx.x) >> 5;
    int lane = threadIdx.x & 31;
    if (w >= Nn) return;
    int grp = lane >> 3;
    int k   = lane & 7;

    int s0 = g_rowptr[w];
    int nE = g_rowptr[w + 1] - s0;

    float acc0 = 0.f, acc1 = 0.f, acc2 = 0.f, acc3 = 0.f;
    float acc4 = 0.f, acc5 = 0.f, acc6 = 0.f, acc7 = 0.f;

    GATHER_STRIP()
    CROSS_GROUP_REDUCE()

    if (grp == 0) {   // lanes 0..7 converged; hold all 64 channels
        float nd = rsqrtf((float)(nE < 1 ? 1 : nE));
        float sc = AC * nd * (1.0f / 32767.0f);
        uint4 lh = __ldg(last + (size_t)w * 8 + k);
        float2 l0 = __half22float2(*(const __half2*)&lh.x);
        float2 l1 = __half22float2(*(const __half2*)&lh.y);
        float2 l2 = __half22float2(*(const __half2*)&lh.z);
        float2 l3 = __half22float2(*(const __half2*)&lh.w);
        float e0 = fminf(fmaxf(fmaf(sc, acc0, l0.x), -1.f), 1.f);
        float e1 = fminf(fmaxf(fmaf(sc, acc1, l0.y), -1.f), 1.f);
        float e2 = fminf(fmaxf(fmaf(sc, acc2, l1.x), -1.f), 1.f);
        float e3 = fminf(fmaxf(fmaf(sc, acc3, l1.y), -1.f), 1.f);
        float e4 = fminf(fmaxf(fmaf(sc, acc4, l2.x), -1.f), 1.f);
        float e5 = fminf(fmaxf(fmaf(sc, acc5, l2.y), -1.f), 1.f);
        float e6 = fminf(fmaxf(fmaf(sc, acc6, l3.x), -1.f), 1.f);
        float e7 = fminf(fmaxf(fmaf(sc, acc7, l3.y), -1.f), 1.f);

        float part = fabsf(e0) + fabsf(e1) + fabsf(e2) + fabsf(e3)
                   + fabsf(e4) + fabsf(e5) + fabsf(e6) + fabsf(e7);
        part += __shfl_xor_sync(0xFFu, part, 1);
        part += __shfl_xor_sync(0xFFu, part, 2);
        part += __shfl_xor_sync(0xFFu, part, 4);

        float sigma = g_sumabs / g_nummask;
        float scale = sigma / part;
        if (isinf(scale) || scale > 1000.f) scale = 1.f;

        const float4* pys = (const float4*)(ys + (size_t)w * Cc + 8 * k);
        const float4* pyt = (const float4*)(yt + (size_t)w * Cc + 8 * k);
        float4 sA = __ldg(pys), sB = __ldg(pys + 1);
        float4 tA = __ldg(pyt), tB = __ldg(pyt + 1);

        float r0 = sA.x + scale * e0; if (isnan(r0)) r0 = sA.x;
        float r1 = sA.y + scale * e1; if (isnan(r1)) r1 = sA.y;
        float r2 = sA.z + scale * e2; if (isnan(r2)) r2 = sA.z;
        float r3 = sA.w + scale * e3; if (isnan(r3)) r3 = sA.w;
        float r4 = sB.x + scale * e4; if (isnan(r4)) r4 = sB.x;
        float r5 = sB.y + scale * e5; if (isnan(r5)) r5 = sB.y;
        float r6 = sB.z + scale * e6; if (isnan(r6)) r6 = sB.z;
        float r7 = sB.w + scale * e7; if (isnan(r7)) r7 = sB.w;
        if (mask_at(mask, w)) {
            r0 = tA.x; r1 = tA.y; r2 = tA.z; r3 = tA.w;
            r4 = tB.x; r5 = tB.y; r6 = tB.z; r7 = tB.w;
        }
        uint4 hy, hl2;
        *(__half2*)&hy.x = __floats2half2_rn(r0, r1);
        *(__half2*)&hy.y = __floats2half2_rn(r2, r3);
        *(__half2*)&hy.z = __floats2half2_rn(r4, r5);
        *(__half2*)&hy.w = __floats2half2_rn(r6, r7);
        float ls = 1.f - AS;
        *(__half2*)&hl2.x = __floats2half2_rn(ls * r0, ls * r1);
        *(__half2*)&hl2.y = __floats2half2_rn(ls * r2, ls * r3);
        *(__half2*)&hl2.z = __floats2half2_rn(ls * r4, ls * r5);
        *(__half2*)&hl2.w = __floats2half2_rn(ls * r6, ls * r7);
        yout[(size_t)w * 8 + k]  = hy;
        lasth[(size_t)w * 8 + k] = hl2;
    }
}

// ---------------- launch ----------------
extern "C" void kernel_launch(void* const* d_in, const int* in_sizes, int n_in,
                              void* d_out, int out_size) {
    const float* y_soft = (const float*)d_in[0];
    const float* y_true = (const float*)d_in[1];
    const int*   src    = (const int*)d_in[2];
    const int*   dst    = (const int*)d_in[3];
    const void*  mask   = (const void*)d_in[4];
    float* out = (float*)d_out;

    const int T = 256;
    const int gE  = (Ee + T - 1) / T;
    const int gE4 = (Ee / 4 + T - 1) / T;
    const int gS  = Nn * 8 / T;              // 3125
    const int gW  = (Nn * 32 + T - 1) / T;   // warp per node

    uint4 *hA, *hB, *lasth;
    cudaGetSymbolAddress((void**)&hA, g_hA);
    cudaGetSymbolAddress((void**)&hB, g_hB);
    cudaGetSymbolAddress((void**)&lasth, g_lasth);

    // preprocessing
    k_init<<<GN, T>>>(mask);
    k_hist<<<gE4, T>>>((const int4*)dst);
    k_scan_a<<<SCAN_NBLK, SCAN_BLK>>>();
    k_scanbc_error<<<gS, T>>>(y_soft, y_true, mask);
    k_fill<<<gE, T>>>(src, dst);

    // correct phase: 9 plain layers + fused 10th(+combine)
    {
        uint4* in = hA; uint4* outp = hB;
        for (int l = 0; l < 9; l++) {
            k_prop16<<<gW, T>>>(in, outp, (float*)0, lasth, AC, -1.f, 1.f);
            uint4* t = in; in = outp; outp = t;
        }
        // in == hB: fused final correct layer + combine -> writes y into hA, lasth
        k_prop_combine<<<gW, T>>>(in, hA, lasth, lasth, y_soft, y_true, mask);
    }

    // smooth phase: 10 layers from hA, final writes fp32 to d_out
    {
        uint4* in = hA; uint4* outp = hB;
        for (int l = 0; l < 9; l++) {
            k_prop16<<<gW, T>>>(in, outp, (float*)0, lasth, AS, 0.f, 1.f);
            uint4* t = in; in = outp; outp = t;
        }
        k_prop16<<<gW, T>>>(in, (uint4*)0, out, lasth, AS, 0.f, 1.f);
    }
    (void)in_sizes; (void)n_in; (void)out_size;
}

// round 12
// speedup vs baseline: 1.5874x; 1.0166x over previous
#include <cuda_runtime.h>
#include <cuda_fp16.h>
#include <math.h>

#define Nn 100000
#define Ee 3200000
#define Cc 64
#define AC 0.979f
#define AS 0.756f
#define SCAN_BLK 1024
#define SCAN_NBLK ((Nn + SCAN_BLK - 1) / SCAN_BLK)   // 98
#define GN ((Nn + 255) / 256)                        // 391

// ---------------- static scratch ----------------
__device__ uint4    g_hA[Nn * 8];      // fp16 state rows: 64 halfs = 128B = 8 uint4
__device__ uint4    g_hB[Nn * 8];
__device__ uint4    g_lasth[Nn * 8];
__device__ int      g_deg[Nn];
__device__ int      g_cnt[Nn];         // pre-initialized to rowptr; fill bumps it
__device__ int      g_rowptr[Nn + 1];
__device__ int      g_wq[Nn];          // 15-bit quantized norm per node
__device__ unsigned g_csr[Ee];         // (wq<<17) | src  — 4B per edge
__device__ int      g_blocksums[128];
__device__ float    g_sumabs;
__device__ float    g_nummask;
__device__ int      g_mask_mode;       // 0=uint8, 1=int32, 2=float32

__device__ __forceinline__ bool mask_at(const void* __restrict__ mp, int i) {
    int mode = g_mask_mode;
    if (mode == 1) return ((const int*)mp)[i] != 0;
    if (mode == 2) return ((const float*)mp)[i] != 0.0f;
    return ((const unsigned char*)mp)[i] != 0;
}

// ---------------- init + mask dtype detection ----------------
__global__ void k_init(const void* __restrict__ mp) {
    cudaTriggerProgrammaticLaunchCompletion();
    int i = blockIdx.x * blockDim.x + threadIdx.x;
    if (i < Nn) g_deg[i] = 0;
    if (i == 0) { g_sumabs = 0.f; g_nummask = 0.f; }
    if (blockIdx.x == 0) {
        __shared__ int s_iok, s_fok;
        if (threadIdx.x == 0) { s_iok = 1; s_fok = 1; }
        __syncthreads();
        const int*   ip = (const int*)mp;
        const float* fp = (const float*)mp;
        bool iok = true, fok = true;
        for (int j = threadIdx.x; j < 1024; j += 256) {
            int v = ip[j];
            if (v != 0 && v != 1) iok = false;
            float f = fp[j];
            if (!(f == 0.0f || f == 1.0f)) fok = false;
        }
        if (!iok) s_iok = 0;
        if (!fok) s_fok = 0;
        __syncthreads();
        if (threadIdx.x == 0) g_mask_mode = s_iok ? 1 : (s_fok ? 2 : 0);
    }
}

// ---------------- degree histogram (4 edges / thread) ----------------
// pre-sync: load dst (static input); post-sync: atomics into g_deg (zeroed by init)
__global__ void k_hist(const int4* __restrict__ dst4) {
    cudaTriggerProgrammaticLaunchCompletion();
    int i = blockIdx.x * blockDim.x + threadIdx.x;
    int4 d = make_int4(0, 0, 0, 0);
    bool act = i < Ee / 4;
    if (act) d = __ldg(&dst4[i]);
    cudaGridDependencySynchronize();
    if (act) {
        atomicAdd(&g_deg[d.x], 1);
        atomicAdd(&g_deg[d.y], 1);
        atomicAdd(&g_deg[d.z], 1);
        atomicAdd(&g_deg[d.w], 1);
    }
}

// ---------------- block-local scan ----------------
__global__ void k_scan_a() {
    cudaTriggerProgrammaticLaunchCompletion();
    cudaGridDependencySynchronize();
    __shared__ int sh[SCAN_BLK];
    int t = threadIdx.x;
    int i = blockIdx.x * SCAN_BLK + t;
    int v = (i < Nn) ? g_deg[i] : 0;
    sh[t] = v;
    __syncthreads();
    for (int off = 1; off < SCAN_BLK; off <<= 1) {
        int x = (t >= off) ? sh[t - off] : 0;
        __syncthreads();
        sh[t] += x;
        __syncthreads();
    }
    if (i < Nn) g_rowptr[i] = sh[t] - v;
    if (t == SCAN_BLK - 1) g_blocksums[blockIdx.x] = sh[t];
}

// ---------------- fused: scan finalize + wq + cnt init + error + reductions ----------------
// pre-sync: load ys/yt/mask (static inputs; g_mask_mode from init, complete 2 kernels back)
__global__ void k_scanbc_error(const float* __restrict__ ys, const float* __restrict__ yt,
                               const void* __restrict__ mask) {
    cudaTriggerProgrammaticLaunchCompletion();
    int t = threadIdx.x;
    int b = blockIdx.x;
    int idx = b * 256 + t;
    bool act = idx < Nn * 8;
    float4 s0v = make_float4(0,0,0,0), s1v = s0v, t0v = s0v, t1v = s0v;
    float m = 0.f;
    if (act) {
        int n = idx >> 3;
        m = mask_at(mask, n) ? 1.f : 0.f;
        const float4* pys = (const float4*)ys + idx * 2;
        const float4* pyt = (const float4*)yt + idx * 2;
        s0v = __ldg(pys); s1v = __ldg(pys + 1);
        t0v = __ldg(pyt); t1v = __ldg(pyt + 1);
    }
    cudaGridDependencySynchronize();

    if (b < GN) {
        __shared__ int sh[128];
        if (t < 128) sh[t] = (t < SCAN_NBLK) ? g_blocksums[t] : 0;
        __syncthreads();
        for (int off = 1; off < 128; off <<= 1) {
            int x = (t >= off && t < 128) ? sh[t - off] : 0;
            __syncthreads();
            if (t < 128) sh[t] += x;
            __syncthreads();
        }
        int i = b * 256 + t;
        if (i < Nn) {
            int blk = i >> 10;
            int add = blk ? sh[blk - 1] : 0;
            int rp = g_rowptr[i] + add;
            g_rowptr[i] = rp;
            g_cnt[i] = rp;                    // fill's running cursor
            int d = g_deg[i]; if (d < 1) d = 1;
            g_wq[i] = (int)(rsqrtf((float)d) * 32767.f + 0.5f);
        }
        if (i == 0) g_rowptr[Nn] = Ee;
        __syncthreads();
    }

    float a = 0.f, cm = 0.f;
    if (act) {
        float e0 = m * (t0v.x - s0v.x), e1 = m * (t0v.y - s0v.y);
        float e2 = m * (t0v.z - s0v.z), e3 = m * (t0v.w - s0v.w);
        float e4 = m * (t1v.x - s1v.x), e5 = m * (t1v.y - s1v.y);
        float e6 = m * (t1v.z - s1v.z), e7 = m * (t1v.w - s1v.w);
        a = fabsf(e0) + fabsf(e1) + fabsf(e2) + fabsf(e3)
          + fabsf(e4) + fabsf(e5) + fabsf(e6) + fabsf(e7);
        uint4 hz, hl;
        *(__half2*)&hz.x = __floats2half2_rn(e0, e1);
        *(__half2*)&hz.y = __floats2half2_rn(e2, e3);
        *(__half2*)&hz.z = __floats2half2_rn(e4, e5);
        *(__half2*)&hz.w = __floats2half2_rn(e6, e7);
        float lc = 1.f - AC;
        *(__half2*)&hl.x = __floats2half2_rn(lc * e0, lc * e1);
        *(__half2*)&hl.y = __floats2half2_rn(lc * e2, lc * e3);
        *(__half2*)&hl.z = __floats2half2_rn(lc * e4, lc * e5);
        *(__half2*)&hl.w = __floats2half2_rn(lc * e6, lc * e7);
        g_hA[idx]    = hz;
        g_lasth[idx] = hl;
        if ((idx & 7) == 0) cm = m;
    }
    for (int o = 16; o; o >>= 1) {
        a  += __shfl_down_sync(0xffffffffu, a, o);
        cm += __shfl_down_sync(0xffffffffu, cm, o);
    }
    __shared__ float sa[8], sc[8];
    int warp = t >> 5, lane = t & 31;
    if (lane == 0) { sa[warp] = a; sc[warp] = cm; }
    __syncthreads();
    if (t == 0) {
        float ta = 0.f, tc = 0.f;
        for (int w = 0; w < 8; w++) { ta += sa[w]; tc += sc[w]; }
        atomicAdd(&g_sumabs, ta);
        atomicAdd(&g_nummask, tc);
    }
}

// ---------------- CSR fill: 1 edge/thread, single atomic cursor ----------------
// pre-sync: load src/dst (static inputs); post-sync: cursor atomic + scatter
__global__ void k_fill(const int* __restrict__ src, const int* __restrict__ dst) {
    cudaTriggerProgrammaticLaunchCompletion();
    int i = blockIdx.x * blockDim.x + threadIdx.x;
    int d = 0, s = 0;
    bool act = i < Ee;
    if (act) { d = dst[i]; s = src[i]; }
    cudaGridDependencySynchronize();
    if (act) {
        int pos = atomicAdd(&g_cnt[d], 1);
        g_csr[pos] = ((unsigned)g_wq[s] << 17) | (unsigned)s;
    }
}

// ---------------- gather macros ----------------
#define GATHER_STEP(J)                                                        \
    if ((J) < cnt) {                                                          \
        unsigned p = __shfl_sync(0xffffffffu, packed, (J) + grp);             \
        int   ss = (int)(p & 0x1FFFFu);                                       \
        float ww = (float)(p >> 17);                                          \
        uint4 h = __ldg(yin + (size_t)ss * 8 + k);                            \
        float2 v0 = __half22float2(*(const __half2*)&h.x);                    \
        float2 v1 = __half22float2(*(const __half2*)&h.y);                    \
        float2 v2 = __half22float2(*(const __half2*)&h.z);                    \
        float2 v3 = __half22float2(*(const __half2*)&h.w);                    \
        acc0 = fmaf(ww, v0.x, acc0);                                          \
        acc1 = fmaf(ww, v0.y, acc1);                                          \
        acc2 = fmaf(ww, v1.x, acc2);                                          \
        acc3 = fmaf(ww, v1.y, acc3);                                          \
        acc4 = fmaf(ww, v2.x, acc4);                                          \
        acc5 = fmaf(ww, v2.y, acc5);                                          \
        acc6 = fmaf(ww, v3.x, acc6);                                          \
        acc7 = fmaf(ww, v3.y, acc7);                                          \
    }

// strip 0's csr word (packed0) was prefetched before gridDependencySync
#define GATHER_STRIP()                                                        \
    for (int base = 0; base < nE; base += 32) {                               \
        unsigned packed = packed0;                                            \
        if (base) packed = (base + lane < nE) ? __ldg(&g_csr[s0 + base + lane]) : 0; \
        int cnt = nE - base;                                                  \
        if (cnt > 32) cnt = 32;                                               \
        GATHER_STEP(0)  GATHER_STEP(4)  GATHER_STEP(8)  GATHER_STEP(12)       \
        GATHER_STEP(16) GATHER_STEP(20) GATHER_STEP(24) GATHER_STEP(28)       \
    }

#define CROSS_GROUP_REDUCE()                                                  \
    _Pragma("unroll")                                                         \
    for (int o = 8; o <= 16; o <<= 1) {                                       \
        acc0 += __shfl_xor_sync(0xffffffffu, acc0, o);                        \
        acc1 += __shfl_xor_sync(0xffffffffu, acc1, o);                        \
        acc2 += __shfl_xor_sync(0xffffffffu, acc2, o);                        \
        acc3 += __shfl_xor_sync(0xffffffffu, acc3, o);                        \
        acc4 += __shfl_xor_sync(0xffffffffu, acc4, o);                        \
        acc5 += __shfl_xor_sync(0xffffffffu, acc5, o);                        \
        acc6 += __shfl_xor_sync(0xffffffffu, acc6, o);                        \
        acc7 += __shfl_xor_sync(0xffffffffu, acc7, o);                        \
    }

// ---------------- propagation layer: warp per node, PDL prefetch ----------------
__global__ void k_prop16(const uint4* __restrict__ yin, uint4* __restrict__ yout,
                         float* __restrict__ out_f,
                         const uint4* __restrict__ last, float alpha, float lo, float hi) {
    cudaTriggerProgrammaticLaunchCompletion();
    int w = (blockIdx.x * blockDim.x + threadIdx.x) >> 5;   // always < Nn (exact grid)
    int lane = threadIdx.x & 31;
    int grp = lane >> 3;
    int k   = lane & 7;

    int s0 = g_rowptr[w];                    // static during prop chain
    int nE = g_rowptr[w + 1] - s0;
    unsigned packed0 = (lane < nE) ? __ldg(&g_csr[s0 + lane]) : 0;   // strip-0 prefetch
    cudaGridDependencySynchronize();

    float acc0 = 0.f, acc1 = 0.f, acc2 = 0.f, acc3 = 0.f;
    float acc4 = 0.f, acc5 = 0.f, acc6 = 0.f, acc7 = 0.f;

    GATHER_STRIP()
    CROSS_GROUP_REDUCE()

    if (grp == 0) {
        float nd = rsqrtf((float)(nE < 1 ? 1 : nE));
        float sc = alpha * nd * (1.0f / 32767.0f);
        uint4 lh = __ldg(last + (size_t)w * 8 + k);
        float2 l0 = __half22float2(*(const __half2*)&lh.x);
        float2 l1 = __half22float2(*(const __half2*)&lh.y);
        float2 l2 = __half22float2(*(const __half2*)&lh.z);
        float2 l3 = __half22float2(*(const __half2*)&lh.w);
        float o0 = fminf(fmaxf(fmaf(sc, acc0, l0.x), lo), hi);
        float o1 = fminf(fmaxf(fmaf(sc, acc1, l0.y), lo), hi);
        float o2 = fminf(fmaxf(fmaf(sc, acc2, l1.x), lo), hi);
        float o3 = fminf(fmaxf(fmaf(sc, acc3, l1.y), lo), hi);
        float o4 = fminf(fmaxf(fmaf(sc, acc4, l2.x), lo), hi);
        float o5 = fminf(fmaxf(fmaf(sc, acc5, l2.y), lo), hi);
        float o6 = fminf(fmaxf(fmaf(sc, acc6, l3.x), lo), hi);
        float o7 = fminf(fmaxf(fmaf(sc, acc7, l3.y), lo), hi);
        if (out_f) {
            float* op = out_f + (size_t)w * Cc + 8 * k;
            *(float4*)(op)     = make_float4(o0, o1, o2, o3);
            *(float4*)(op + 4) = make_float4(o4, o5, o6, o7);
        } else {
            uint4 hout;
            *(__half2*)&hout.x = __floats2half2_rn(o0, o1);
            *(__half2*)&hout.y = __floats2half2_rn(o2, o3);
            *(__half2*)&hout.z = __floats2half2_rn(o4, o5);
            *(__half2*)&hout.w = __floats2half2_rn(o6, o7);
            yout[(size_t)w * 8 + k] = hout;
        }
    }
}

// ---------------- final correct layer fused with combine ----------------
__global__ void k_prop_combine(const uint4* __restrict__ yin, uint4* __restrict__ yout,
                               uint4* __restrict__ lasth,
                               const uint4* __restrict__ last,
                               const float* __restrict__ ys, const float* __restrict__ yt,
                               const void* __restrict__ mask) {
    cudaTriggerProgrammaticLaunchCompletion();
    int w = (blockIdx.x * blockDim.x + threadIdx.x) >> 5;
    int lane = threadIdx.x & 31;
    int grp = lane >> 3;
    int k   = lane & 7;

    int s0 = g_rowptr[w];
    int nE = g_rowptr[w + 1] - s0;
    unsigned packed0 = (lane < nE) ? __ldg(&g_csr[s0 + lane]) : 0;
    cudaGridDependencySynchronize();

    float acc0 = 0.f, acc1 = 0.f, acc2 = 0.f, acc3 = 0.f;
    float acc4 = 0.f, acc5 = 0.f, acc6 = 0.f, acc7 = 0.f;

    GATHER_STRIP()
    CROSS_GROUP_REDUCE()

    if (grp == 0) {   // lanes 0..7 converged; hold all 64 channels
        float nd = rsqrtf((float)(nE < 1 ? 1 : nE));
        float sc = AC * nd * (1.0f / 32767.0f);
        uint4 lh = __ldg(last + (size_t)w * 8 + k);
        float2 l0 = __half22float2(*(const __half2*)&lh.x);
        float2 l1 = __half22float2(*(const __half2*)&lh.y);
        float2 l2 = __half22float2(*(const __half2*)&lh.z);
        float2 l3 = __half22float2(*(const __half2*)&lh.w);
        float e0 = fminf(fmaxf(fmaf(sc, acc0, l0.x), -1.f), 1.f);
        float e1 = fminf(fmaxf(fmaf(sc, acc1, l0.y), -1.f), 1.f);
        float e2 = fminf(fmaxf(fmaf(sc, acc2, l1.x), -1.f), 1.f);
        float e3 = fminf(fmaxf(fmaf(sc, acc3, l1.y), -1.f), 1.f);
        float e4 = fminf(fmaxf(fmaf(sc, acc4, l2.x), -1.f), 1.f);
        float e5 = fminf(fmaxf(fmaf(sc, acc5, l2.y), -1.f), 1.f);
        float e6 = fminf(fmaxf(fmaf(sc, acc6, l3.x), -1.f), 1.f);
        float e7 = fminf(fmaxf(fmaf(sc, acc7, l3.y), -1.f), 1.f);

        float part = fabsf(e0) + fabsf(e1) + fabsf(e2) + fabsf(e3)
                   + fabsf(e4) + fabsf(e5) + fabsf(e6) + fabsf(e7);
        part += __shfl_xor_sync(0xFFu, part, 1);
        part += __shfl_xor_sync(0xFFu, part, 2);
        part += __shfl_xor_sync(0xFFu, part, 4);

        float sigma = g_sumabs / g_nummask;
        float scale = sigma / part;
        if (isinf(scale) || scale > 1000.f) scale = 1.f;

        const float4* pys = (const float4*)(ys + (size_t)w * Cc + 8 * k);
        const float4* pyt = (const float4*)(yt + (size_t)w * Cc + 8 * k);
        float4 sA = __ldg(pys), sB = __ldg(pys + 1);
        float4 tA = __ldg(pyt), tB = __ldg(pyt + 1);

        float r0 = sA.x + scale * e0; if (isnan(r0)) r0 = sA.x;
        float r1 = sA.y + scale * e1; if (isnan(r1)) r1 = sA.y;
        float r2 = sA.z + scale * e2; if (isnan(r2)) r2 = sA.z;
        float r3 = sA.w + scale * e3; if (isnan(r3)) r3 = sA.w;
        float r4 = sB.x + scale * e4; if (isnan(r4)) r4 = sB.x;
        float r5 = sB.y + scale * e5; if (isnan(r5)) r5 = sB.y;
        float r6 = sB.z + scale * e6; if (isnan(r6)) r6 = sB.z;
        float r7 = sB.w + scale * e7; if (isnan(r7)) r7 = sB.w;
        if (mask_at(mask, w)) {
            r0 = tA.x; r1 = tA.y; r2 = tA.z; r3 = tA.w;
            r4 = tB.x; r5 = tB.y; r6 = tB.z; r7 = tB.w;
        }
        uint4 hy, hl2;
        *(__half2*)&hy.x = __floats2half2_rn(r0, r1);
        *(__half2*)&hy.y = __floats2half2_rn(r2, r3);
        *(__half2*)&hy.z = __floats2half2_rn(r4, r5);
        *(__half2*)&hy.w = __floats2half2_rn(r6, r7);
        float ls = 1.f - AS;
        *(__half2*)&hl2.x = __floats2half2_rn(ls * r0, ls * r1);
        *(__half2*)&hl2.y = __floats2half2_rn(ls * r2, ls * r3);
        *(__half2*)&hl2.z = __floats2half2_rn(ls * r4, ls * r5);
        *(__half2*)&hl2.w = __floats2half2_rn(ls * r6, ls * r7);
        yout[(size_t)w * 8 + k]  = hy;
        lasth[(size_t)w * 8 + k] = hl2;
    }
}

// ---------------- launch ----------------
static inline void mk_cfg(cudaLaunchConfig_t* cfg, cudaLaunchAttribute* attr,
                          int grid, int block, int pdl) {
    cfg->gridDim = dim3((unsigned)grid, 1, 1);
    cfg->blockDim = dim3((unsigned)block, 1, 1);
    cfg->dynamicSmemBytes = 0;
    cfg->stream = 0;
    attr->id = cudaLaunchAttributeProgrammaticStreamSerialization;
    attr->val.programmaticStreamSerializationAllowed = 1;
    cfg->attrs = attr;
    cfg->numAttrs = pdl ? 1 : 0;
}

extern "C" void kernel_launch(void* const* d_in, const int* in_sizes, int n_in,
                              void* d_out, int out_size) {
    const float* y_soft = (const float*)d_in[0];
    const float* y_true = (const float*)d_in[1];
    const int*   src    = (const int*)d_in[2];
    const int*   dst    = (const int*)d_in[3];
    const void*  mask   = (const void*)d_in[4];
    float* out = (float*)d_out;

    const int T = 256;
    const int gE  = (Ee + T - 1) / T;
    const int gE4 = (Ee / 4 + T - 1) / T;
    const int gS  = Nn * 8 / T;              // 3125
    const int gW  = (Nn * 32 + T - 1) / T;   // warp per node (exactly 12500)

    uint4 *hA, *hB, *lasth;
    cudaGetSymbolAddress((void**)&hA, g_hA);
    cudaGetSymbolAddress((void**)&hB, g_hB);
    cudaGetSymbolAddress((void**)&lasth, g_lasth);

    cudaLaunchConfig_t cfg;
    cudaLaunchAttribute attr;

    // preprocessing
    mk_cfg(&cfg, &attr, GN, T, 0);
    cudaLaunchKernelEx(&cfg, k_init, mask);
    mk_cfg(&cfg, &attr, gE4, T, 1);
    cudaLaunchKernelEx(&cfg, k_hist, (const int4*)dst);
    mk_cfg(&cfg, &attr, SCAN_NBLK, SCAN_BLK, 1);
    cudaLaunchKernelEx(&cfg, k_scan_a);
    mk_cfg(&cfg, &attr, gS, T, 1);
    cudaLaunchKernelEx(&cfg, k_scanbc_error, y_soft, y_true, mask);
    mk_cfg(&cfg, &attr, gE, T, 1);
    cudaLaunchKernelEx(&cfg, k_fill, src, dst);

    // correct phase: 9 plain layers + fused 10th(+combine)
    {
        uint4* in = hA; uint4* outp = hB;
        for (int l = 0; l < 9; l++) {
            // layer 0 must be fully serialized: its pre-sync csr prefetch
            // would otherwise race k_fill's csr writes
            mk_cfg(&cfg, &attr, gW, T, l == 0 ? 0 : 1);
            cudaLaunchKernelEx(&cfg, k_prop16,
                               (const uint4*)in, outp, (float*)0,
                               (const uint4*)lasth, AC, -1.f, 1.f);
            uint4* t = in; in = outp; outp = t;
        }
        // in == hB: fused final correct layer + combine -> writes y into hA, lasth
        mk_cfg(&cfg, &attr, gW, T, 1);
        cudaLaunchKernelEx(&cfg, k_prop_combine,
                           (const uint4*)in, hA, lasth, (const uint4*)lasth,
                           y_soft, y_true, mask);
    }

    // smooth phase: 10 layers from hA, final writes fp32 to d_out
    {
        uint4* in = hA; uint4* outp = hB;
        for (int l = 0; l < 9; l++) {
            mk_cfg(&cfg, &attr, gW, T, 1);
            cudaLaunchKernelEx(&cfg, k_prop16,
                               (const uint4*)in, outp, (float*)0,
                               (const uint4*)lasth, AS, 0.f, 1.f);
            uint4* t = in; in = outp; outp = t;
        }
        mk_cfg(&cfg, &attr, gW, T, 1);
        cudaLaunchKernelEx(&cfg, k_prop16,
                           (const uint4*)in, (uint4*)0, out,
                           (const uint4*)lasth, AS, 0.f, 1.f);
    }
    (void)in_sizes; (void)n_in; (void)out_size;
}

// round 14
// speedup vs baseline: 1.6206x; 1.0209x over previous
#include <cuda_runtime.h>
#include <cuda_fp16.h>
#include <math.h>

#define Nn 100000
#define Ee 3200000
#define Cc 64
#define AC 0.979f
#define AS 0.756f
#define SCAN_BLK 1024
#define SCAN_NBLK ((Nn + SCAN_BLK - 1) / SCAN_BLK)   // 98
#define GN ((Nn + 255) / 256)                        // 391
#define TP 128                                       // prop-kernel block size

// ---------------- static scratch ----------------
__device__ uint4    g_hA[Nn * 8];      // fp16 state rows: 64 halfs = 128B = 8 uint4
__device__ uint4    g_hB[Nn * 8];
__device__ uint4    g_lasth[Nn * 8];
__device__ int      g_deg[Nn];
__device__ int      g_cnt[Nn];         // pre-initialized to rowptr; fill bumps it
__device__ int      g_rowptr[Nn + 1];
__device__ int      g_wq[Nn];          // 15-bit quantized norm per node
__device__ unsigned g_csr[Ee];         // (wq<<17) | src  — 4B per edge
__device__ int      g_blocksums[128];
__device__ float    g_sumabs;
__device__ float    g_nummask;
__device__ int      g_mask_mode;       // 0=uint8, 1=int32, 2=float32

__device__ __forceinline__ bool mask_at(const void* __restrict__ mp, int i) {
    int mode = g_mask_mode;
    if (mode == 1) return ((const int*)mp)[i] != 0;
    if (mode == 2) return ((const float*)mp)[i] != 0.0f;
    return ((const unsigned char*)mp)[i] != 0;
}

// ---------------- init + mask dtype detection ----------------
__global__ void k_init(const void* __restrict__ mp) {
    cudaTriggerProgrammaticLaunchCompletion();
    int i = blockIdx.x * blockDim.x + threadIdx.x;
    if (i < Nn) g_deg[i] = 0;
    if (i == 0) { g_sumabs = 0.f; g_nummask = 0.f; }
    if (blockIdx.x == 0) {
        __shared__ int s_iok, s_fok;
        if (threadIdx.x == 0) { s_iok = 1; s_fok = 1; }
        __syncthreads();
        const int*   ip = (const int*)mp;
        const float* fp = (const float*)mp;
        bool iok = true, fok = true;
        for (int j = threadIdx.x; j < 1024; j += 256) {
            int v = ip[j];
            if (v != 0 && v != 1) iok = false;
            float f = fp[j];
            if (!(f == 0.0f || f == 1.0f)) fok = false;
        }
        if (!iok) s_iok = 0;
        if (!fok) s_fok = 0;
        __syncthreads();
        if (threadIdx.x == 0) g_mask_mode = s_iok ? 1 : (s_fok ? 2 : 0);
    }
}

// ---------------- degree histogram (4 edges / thread) ----------------
__global__ void k_hist(const int4* __restrict__ dst4) {
    cudaTriggerProgrammaticLaunchCompletion();
    int i = blockIdx.x * blockDim.x + threadIdx.x;
    int4 d = make_int4(0, 0, 0, 0);
    bool act = i < Ee / 4;
    if (act) d = __ldg(&dst4[i]);
    cudaGridDependencySynchronize();
    if (act) {
        atomicAdd(&g_deg[d.x], 1);
        atomicAdd(&g_deg[d.y], 1);
        atomicAdd(&g_deg[d.z], 1);
        atomicAdd(&g_deg[d.w], 1);
    }
}

// ---------------- block-local scan ----------------
__global__ void k_scan_a() {
    cudaTriggerProgrammaticLaunchCompletion();
    cudaGridDependencySynchronize();
    __shared__ int sh[SCAN_BLK];
    int t = threadIdx.x;
    int i = blockIdx.x * SCAN_BLK + t;
    int v = (i < Nn) ? g_deg[i] : 0;
    sh[t] = v;
    __syncthreads();
    for (int off = 1; off < SCAN_BLK; off <<= 1) {
        int x = (t >= off) ? sh[t - off] : 0;
        __syncthreads();
        sh[t] += x;
        __syncthreads();
    }
    if (i < Nn) g_rowptr[i] = sh[t] - v;
    if (t == SCAN_BLK - 1) g_blocksums[blockIdx.x] = sh[t];
}

// ---------------- fused: scan finalize + wq + cnt init + error + reductions ----------------
__global__ void k_scanbc_error(const float* __restrict__ ys, const float* __restrict__ yt,
                               const void* __restrict__ mask) {
    cudaTriggerProgrammaticLaunchCompletion();
    int t = threadIdx.x;
    int b = blockIdx.x;
    int idx = b * 256 + t;
    bool act = idx < Nn * 8;
    float4 s0v = make_float4(0,0,0,0), s1v = s0v, t0v = s0v, t1v = s0v;
    float m = 0.f;
    if (act) {
        int n = idx >> 3;
        m = mask_at(mask, n) ? 1.f : 0.f;
        const float4* pys = (const float4*)ys + idx * 2;
        const float4* pyt = (const float4*)yt + idx * 2;
        s0v = __ldg(pys); s1v = __ldg(pys + 1);
        t0v = __ldg(pyt); t1v = __ldg(pyt + 1);
    }
    cudaGridDependencySynchronize();

    if (b < GN) {
        __shared__ int sh[128];
        if (t < 128) sh[t] = (t < SCAN_NBLK) ? g_blocksums[t] : 0;
        __syncthreads();
        for (int off = 1; off < 128; off <<= 1) {
            int x = (t >= off && t < 128) ? sh[t - off] : 0;
            __syncthreads();
            if (t < 128) sh[t] += x;
            __syncthreads();
        }
        int i = b * 256 + t;
        if (i < Nn) {
            int blk = i >> 10;
            int add = blk ? sh[blk - 1] : 0;
            int rp = g_rowptr[i] + add;
            g_rowptr[i] = rp;
            g_cnt[i] = rp;                    // fill's running cursor
            int d = g_deg[i]; if (d < 1) d = 1;
            g_wq[i] = (int)(rsqrtf((float)d) * 32767.f + 0.5f);
        }
        if (i == 0) g_rowptr[Nn] = Ee;
        __syncthreads();
    }

    float a = 0.f, cm = 0.f;
    if (act) {
        float e0 = m * (t0v.x - s0v.x), e1 = m * (t0v.y - s0v.y);
        float e2 = m * (t0v.z - s0v.z), e3 = m * (t0v.w - s0v.w);
        float e4 = m * (t1v.x - s1v.x), e5 = m * (t1v.y - s1v.y);
        float e6 = m * (t1v.z - s1v.z), e7 = m * (t1v.w - s1v.w);
        a = fabsf(e0) + fabsf(e1) + fabsf(e2) + fabsf(e3)
          + fabsf(e4) + fabsf(e5) + fabsf(e6) + fabsf(e7);
        uint4 hz, hl;
        *(__half2*)&hz.x = __floats2half2_rn(e0, e1);
        *(__half2*)&hz.y = __floats2half2_rn(e2, e3);
        *(__half2*)&hz.z = __floats2half2_rn(e4, e5);
        *(__half2*)&hz.w = __floats2half2_rn(e6, e7);
        float lc = 1.f - AC;
        *(__half2*)&hl.x = __floats2half2_rn(lc * e0, lc * e1);
        *(__half2*)&hl.y = __floats2half2_rn(lc * e2, lc * e3);
        *(__half2*)&hl.z = __floats2half2_rn(lc * e4, lc * e5);
        *(__half2*)&hl.w = __floats2half2_rn(lc * e6, lc * e7);
        g_hA[idx]    = hz;
        g_lasth[idx] = hl;
        if ((idx & 7) == 0) cm = m;
    }
    for (int o = 16; o; o >>= 1) {
        a  += __shfl_down_sync(0xffffffffu, a, o);
        cm += __shfl_down_sync(0xffffffffu, cm, o);
    }
    __shared__ float sa[8], sc[8];
    int warp = t >> 5, lane = t & 31;
    if (lane == 0) { sa[warp] = a; sc[warp] = cm; }
    __syncthreads();
    if (t == 0) {
        float ta = 0.f, tc = 0.f;
        for (int w = 0; w < 8; w++) { ta += sa[w]; tc += sc[w]; }
        atomicAdd(&g_sumabs, ta);
        atomicAdd(&g_nummask, tc);
    }
}

// ---------------- CSR fill: 1 edge/thread, single atomic cursor ----------------
__global__ void k_fill(const int* __restrict__ src, const int* __restrict__ dst) {
    cudaTriggerProgrammaticLaunchCompletion();
    int i = blockIdx.x * blockDim.x + threadIdx.x;
    int d = 0, s = 0;
    bool act = i < Ee;
    if (act) { d = dst[i]; s = src[i]; }
    cudaGridDependencySynchronize();
    if (act) {
        int pos = atomicAdd(&g_cnt[d], 1);
        g_csr[pos] = ((unsigned)g_wq[s] << 17) | (unsigned)s;
    }
}

// ---------------- gather macros ----------------
#define GATHER_STEP(J)                                                        \
    if ((J) < cnt) {                                                          \
        unsigned p = __shfl_sync(0xffffffffu, packed, (J) + grp);             \
        int   ss = (int)(p & 0x1FFFFu);                                       \
        float ww = (float)(p >> 17);                                          \
        uint4 h = __ldg(yin + (size_t)ss * 8 + k);                            \
        float2 v0 = __half22float2(*(const __half2*)&h.x);                    \
        float2 v1 = __half22float2(*(const __half2*)&h.y);                    \
        float2 v2 = __half22float2(*(const __half2*)&h.z);                    \
        float2 v3 = __half22float2(*(const __half2*)&h.w);                    \
        acc0 = fmaf(ww, v0.x, acc0);                                          \
        acc1 = fmaf(ww, v0.y, acc1);                                          \
        acc2 = fmaf(ww, v1.x, acc2);                                          \
        acc3 = fmaf(ww, v1.y, acc3);                                          \
        acc4 = fmaf(ww, v2.x, acc4);                                          \
        acc5 = fmaf(ww, v2.y, acc5);                                          \
        acc6 = fmaf(ww, v3.x, acc6);                                          \
        acc7 = fmaf(ww, v3.y, acc7);                                          \
    }

// strip 0's csr word (packed0) was prefetched before gridDependencySync
#define GATHER_STRIP()                                                        \
    for (int base = 0; base < nE; base += 32) {                               \
        unsigned packed = packed0;                                            \
        if (base) packed = (base + lane < nE) ? __ldg(&g_csr[s0 + base + lane]) : 0; \
        int cnt = nE - base;                                                  \
        if (cnt > 32) cnt = 32;                                               \
        GATHER_STEP(0)  GATHER_STEP(4)  GATHER_STEP(8)  GATHER_STEP(12)       \
        GATHER_STEP(16) GATHER_STEP(20) GATHER_STEP(24) GATHER_STEP(28)       \
    }

#define CROSS_GROUP_REDUCE()                                                  \
    _Pragma("unroll")                                                         \
    for (int o = 8; o <= 16; o <<= 1) {                                       \
        acc0 += __shfl_xor_sync(0xffffffffu, acc0, o);                        \
        acc1 += __shfl_xor_sync(0xffffffffu, acc1, o);                        \
        acc2 += __shfl_xor_sync(0xffffffffu, acc2, o);                        \
        acc3 += __shfl_xor_sync(0xffffffffu, acc3, o);                        \
        acc4 += __shfl_xor_sync(0xffffffffu, acc4, o);                        \
        acc5 += __shfl_xor_sync(0xffffffffu, acc5, o);                        \
        acc6 += __shfl_xor_sync(0xffffffffu, acc6, o);                        \
        acc7 += __shfl_xor_sync(0xffffffffu, acc7, o);                        \
    }

// ---------------- propagation layer: warp per node, PDL prefetch, 128-thread CTAs ----------------
__global__ void __launch_bounds__(TP)
k_prop16(const uint4* __restrict__ yin, uint4* __restrict__ yout,
         float* __restrict__ out_f,
         const uint4* __restrict__ last, float alpha, float lo, float hi) {
    cudaTriggerProgrammaticLaunchCompletion();
    int w = (blockIdx.x * TP + threadIdx.x) >> 5;   // always < Nn (exact grid)
    int lane = threadIdx.x & 31;
    int grp = lane >> 3;
    int k   = lane & 7;

    int s0 = g_rowptr[w];                    // static during prop chain
    int nE = g_rowptr[w + 1] - s0;
    unsigned packed0 = (lane < nE) ? __ldg(&g_csr[s0 + lane]) : 0;   // strip-0 prefetch
    cudaGridDependencySynchronize();

    float acc0 = 0.f, acc1 = 0.f, acc2 = 0.f, acc3 = 0.f;
    float acc4 = 0.f, acc5 = 0.f, acc6 = 0.f, acc7 = 0.f;

    GATHER_STRIP()
    CROSS_GROUP_REDUCE()

    if (grp == 0) {
        float nd = rsqrtf((float)(nE < 1 ? 1 : nE));
        float sc = alpha * nd * (1.0f / 32767.0f);
        uint4 lh = __ldg(last + (size_t)w * 8 + k);
        float2 l0 = __half22float2(*(const __half2*)&lh.x);
        float2 l1 = __half22float2(*(const __half2*)&lh.y);
        float2 l2 = __half22float2(*(const __half2*)&lh.z);
        float2 l3 = __half22float2(*(const __half2*)&lh.w);
        float o0 = fminf(fmaxf(fmaf(sc, acc0, l0.x), lo), hi);
        float o1 = fminf(fmaxf(fmaf(sc, acc1, l0.y), lo), hi);
        float o2 = fminf(fmaxf(fmaf(sc, acc2, l1.x), lo), hi);
        float o3 = fminf(fmaxf(fmaf(sc, acc3, l1.y), lo), hi);
        float o4 = fminf(fmaxf(fmaf(sc, acc4, l2.x), lo), hi);
        float o5 = fminf(fmaxf(fmaf(sc, acc5, l2.y), lo), hi);
        float o6 = fminf(fmaxf(fmaf(sc, acc6, l3.x), lo), hi);
        float o7 = fminf(fmaxf(fmaf(sc, acc7, l3.y), lo), hi);
        if (out_f) {
            float* op = out_f + (size_t)w * Cc + 8 * k;
            *(float4*)(op)     = make_float4(o0, o1, o2, o3);
            *(float4*)(op + 4) = make_float4(o4, o5, o6, o7);
        } else {
            uint4 hout;
            *(__half2*)&hout.x = __floats2half2_rn(o0, o1);
            *(__half2*)&hout.y = __floats2half2_rn(o2, o3);
            *(__half2*)&hout.z = __floats2half2_rn(o4, o5);
            *(__half2*)&hout.w = __floats2half2_rn(o6, o7);
            yout[(size_t)w * 8 + k] = hout;
        }
    }
}

// ---------------- final correct layer fused with combine ----------------
__global__ void __launch_bounds__(TP)
k_prop_combine(const uint4* __restrict__ yin, uint4* __restrict__ yout,
               uint4* __restrict__ lasth,
               const uint4* __restrict__ last,
               const float* __restrict__ ys, const float* __restrict__ yt,
               const void* __restrict__ mask) {
    cudaTriggerProgrammaticLaunchCompletion();
    int w = (blockIdx.x * TP + threadIdx.x) >> 5;
    int lane = threadIdx.x & 31;
    int grp = lane >> 3;
    int k   = lane & 7;

    int s0 = g_rowptr[w];
    int nE = g_rowptr[w + 1] - s0;
    unsigned packed0 = (lane < nE) ? __ldg(&g_csr[s0 + lane]) : 0;
    cudaGridDependencySynchronize();

    float acc0 = 0.f, acc1 = 0.f, acc2 = 0.f, acc3 = 0.f;
    float acc4 = 0.f, acc5 = 0.f, acc6 = 0.f, acc7 = 0.f;

    GATHER_STRIP()
    CROSS_GROUP_REDUCE()

    if (grp == 0) {   // lanes 0..7 converged; hold all 64 channels
        float nd = rsqrtf((float)(nE < 1 ? 1 : nE));
        float sc = AC * nd * (1.0f / 32767.0f);
        uint4 lh = __ldg(last + (size_t)w * 8 + k);
        float2 l0 = __half22float2(*(const __half2*)&lh.x);
        float2 l1 = __half22float2(*(const __half2*)&lh.y);
        float2 l2 = __half22float2(*(const __half2*)&lh.z);
        float2 l3 = __half22float2(*(const __half2*)&lh.w);
        float e0 = fminf(fmaxf(fmaf(sc, acc0, l0.x), -1.f), 1.f);
        float e1 = fminf(fmaxf(fmaf(sc, acc1, l0.y), -1.f), 1.f);
        float e2 = fminf(fmaxf(fmaf(sc, acc2, l1.x), -1.f), 1.f);
        float e3 = fminf(fmaxf(fmaf(sc, acc3, l1.y), -1.f), 1.f);
        float e4 = fminf(fmaxf(fmaf(sc, acc4, l2.x), -1.f), 1.f);
        float e5 = fminf(fmaxf(fmaf(sc, acc5, l2.y), -1.f), 1.f);
        float e6 = fminf(fmaxf(fmaf(sc, acc6, l3.x), -1.f), 1.f);
        float e7 = fminf(fmaxf(fmaf(sc, acc7, l3.y), -1.f), 1.f);

        float part = fabsf(e0) + fabsf(e1) + fabsf(e2) + fabsf(e3)
                   + fabsf(e4) + fabsf(e5) + fabsf(e6) + fabsf(e7);
        part += __shfl_xor_sync(0xFFu, part, 1);
        part += __shfl_xor_sync(0xFFu, part, 2);
        part += __shfl_xor_sync(0xFFu, part, 4);

        float sigma = g_sumabs / g_nummask;
        float scale = sigma / part;
        if (isinf(scale) || scale > 1000.f) scale = 1.f;

        const float4* pys = (const float4*)(ys + (size_t)w * Cc + 8 * k);
        const float4* pyt = (const float4*)(yt + (size_t)w * Cc + 8 * k);
        float4 sA = __ldg(pys), sB = __ldg(pys + 1);
        float4 tA = __ldg(pyt), tB = __ldg(pyt + 1);

        float r0 = sA.x + scale * e0; if (isnan(r0)) r0 = sA.x;
        float r1 = sA.y + scale * e1; if (isnan(r1)) r1 = sA.y;
        float r2 = sA.z + scale * e2; if (isnan(r2)) r2 = sA.z;
        float r3 = sA.w + scale * e3; if (isnan(r3)) r3 = sA.w;
        float r4 = sB.x + scale * e4; if (isnan(r4)) r4 = sB.x;
        float r5 = sB.y + scale * e5; if (isnan(r5)) r5 = sB.y;
        float r6 = sB.z + scale * e6; if (isnan(r6)) r6 = sB.z;
        float r7 = sB.w + scale * e7; if (isnan(r7)) r7 = sB.w;
        if (mask_at(mask, w)) {
            r0 = tA.x; r1 = tA.y; r2 = tA.z; r3 = tA.w;
            r4 = tB.x; r5 = tB.y; r6 = tB.z; r7 = tB.w;
        }
        uint4 hy, hl2;
        *(__half2*)&hy.x = __floats2half2_rn(r0, r1);
        *(__half2*)&hy.y = __floats2half2_rn(r2, r3);
        *(__half2*)&hy.z = __floats2half2_rn(r4, r5);
        *(__half2*)&hy.w = __floats2half2_rn(r6, r7);
        float ls = 1.f - AS;
        *(__half2*)&hl2.x = __floats2half2_rn(ls * r0, ls * r1);
        *(__half2*)&hl2.y = __floats2half2_rn(ls * r2, ls * r3);
        *(__half2*)&hl2.z = __floats2half2_rn(ls * r4, ls * r5);
        *(__half2*)&hl2.w = __floats2half2_rn(ls * r6, ls * r7);
        yout[(size_t)w * 8 + k]  = hy;
        lasth[(size_t)w * 8 + k] = hl2;
    }
}

// ---------------- launch ----------------
static inline void mk_cfg(cudaLaunchConfig_t* cfg, cudaLaunchAttribute* attr,
                          int grid, int block, int pdl) {
    cfg->gridDim = dim3((unsigned)grid, 1, 1);
    cfg->blockDim = dim3((unsigned)block, 1, 1);
    cfg->dynamicSmemBytes = 0;
    cfg->stream = 0;
    attr->id = cudaLaunchAttributeProgrammaticStreamSerialization;
    attr->val.programmaticStreamSerializationAllowed = 1;
    cfg->attrs = attr;
    cfg->numAttrs = pdl ? 1 : 0;
}

extern "C" void kernel_launch(void* const* d_in, const int* in_sizes, int n_in,
                              void* d_out, int out_size) {
    const float* y_soft = (const float*)d_in[0];
    const float* y_true = (const float*)d_in[1];
    const int*   src    = (const int*)d_in[2];
    const int*   dst    = (const int*)d_in[3];
    const void*  mask   = (const void*)d_in[4];
    float* out = (float*)d_out;

    const int T = 256;
    const int gE  = (Ee + T - 1) / T;
    const int gE4 = (Ee / 4 + T - 1) / T;
    const int gS  = Nn * 8 / T;              // 3125
    const int gW  = Nn * 32 / TP;            // 25000 blocks of 128 (4 warps)

    uint4 *hA, *hB, *lasth;
    cudaGetSymbolAddress((void**)&hA, g_hA);
    cudaGetSymbolAddress((void**)&hB, g_hB);
    cudaGetSymbolAddress((void**)&lasth, g_lasth);

    cudaLaunchConfig_t cfg;
    cudaLaunchAttribute attr;

    // preprocessing
    mk_cfg(&cfg, &attr, GN, T, 0);
    cudaLaunchKernelEx(&cfg, k_init, mask);
    mk_cfg(&cfg, &attr, gE4, T, 1);
    cudaLaunchKernelEx(&cfg, k_hist, (const int4*)dst);
    mk_cfg(&cfg, &attr, SCAN_NBLK, SCAN_BLK, 1);
    cudaLaunchKernelEx(&cfg, k_scan_a);
    mk_cfg(&cfg, &attr, gS, T, 1);
    cudaLaunchKernelEx(&cfg, k_scanbc_error, y_soft, y_true, mask);
    mk_cfg(&cfg, &attr, gE, T, 1);
    cudaLaunchKernelEx(&cfg, k_fill, src, dst);

    // correct phase: 9 plain layers + fused 10th(+combine)
    {
        uint4* in = hA; uint4* outp = hB;
        for (int l = 0; l < 9; l++) {
            // layer 0 must be fully serialized: its pre-sync csr prefetch
            // would otherwise race k_fill's csr writes
            mk_cfg(&cfg, &attr, gW, TP, l == 0 ? 0 : 1);
            cudaLaunchKernelEx(&cfg, k_prop16,
                               (const uint4*)in, outp, (float*)0,
                               (const uint4*)lasth, AC, -1.f, 1.f);
            uint4* t = in; in = outp; outp = t;
        }
        // in == hB: fused final correct layer + combine -> writes y into hA, lasth
        mk_cfg(&cfg, &attr, gW, TP, 1);
        cudaLaunchKernelEx(&cfg, k_prop_combine,
                           (const uint4*)in, hA, lasth, (const uint4*)lasth,
                           y_soft, y_true, mask);
    }

    // smooth phase: 10 layers from hA, final writes fp32 to d_out
    {
        uint4* in = hA; uint4* outp = hB;
        for (int l = 0; l < 9; l++) {
            mk_cfg(&cfg, &attr, gW, TP, 1);
            cudaLaunchKernelEx(&cfg, k_prop16,
                               (const uint4*)in, outp, (float*)0,
                               (const uint4*)lasth, AS, 0.f, 1.f);
            uint4* t = in; in = outp; outp = t;
        }
        mk_cfg(&cfg, &attr, gW, TP, 1);
        cudaLaunchKernelEx(&cfg, k_prop16,
                           (const uint4*)in, (uint4*)0, out,
                           (const uint4*)lasth, AS, 0.f, 1.f);
    }
    (void)in_sizes; (void)n_in; (void)out_size;
}